// round 11
// baseline (speedup 1.0000x reference)
#include <cuda_runtime.h>
#include <cuda_bf16.h>
#include <cstdint>

// Problem: H[8,4096,1024] G[8,1024,768] Wq[256,768] Wk[256,1024] -> Z[8,1024,1024]
#define B_  8
#define L_  4096
#define DH_ 1024
#define T_  1024
#define DG_ 768
#define P_  256

// Fixed-point scales: lambda = 2^-12 for Q, K, H, and P (range +-8 / [0,16))
#define INV_LAM   4096.0f
#define LAM       2.44140625e-4f     // 2^-12
#define SCALE_S   3.7252903e-09f     // 2^-28 = lamQ*lamK/16
#define SCALE_PV  5.9604645e-08f     // 2^-24 = lamP*lamH

// ---------------------------------------------------------------------------
// PTX helpers — base-target (sm_80+): mma.sync, ldmatrix, cp.async
// ---------------------------------------------------------------------------
__device__ __forceinline__ uint32_t smem_to_u32(const void* p) {
    uint32_t a;
    asm("{ .reg .u64 t; cvta.to.shared.u64 t, %1; cvt.u32.u64 %0, t; }" : "=r"(a) : "l"(p));
    return a;
}
#define CP_ASYNC16(sa, g) \
    asm volatile("cp.async.cg.shared.global [%0], [%1], 16;" :: "r"(sa), "l"(g))
#define CP_COMMIT() asm volatile("cp.async.commit_group;")
#define CP_WAIT1()  asm volatile("cp.async.wait_group 1;")

#define LDSM_X4(r0, r1, r2, r3, addr) \
    asm volatile("ldmatrix.sync.aligned.m8n8.x4.shared.b16 {%0,%1,%2,%3}, [%4];" \
                 : "=r"(r0), "=r"(r1), "=r"(r2), "=r"(r3) : "r"(addr))

__device__ __forceinline__ void mma16816(float* d, const uint32_t* a, const uint32_t* b) {
    asm volatile(
        "mma.sync.aligned.m16n8k16.row.col.f32.bf16.bf16.f32 "
        "{%0,%1,%2,%3}, {%4,%5,%6,%7}, {%8,%9}, {%0,%1,%2,%3};"
        : "+f"(d[0]), "+f"(d[1]), "+f"(d[2]), "+f"(d[3])
        : "r"(a[0]), "r"(a[1]), "r"(a[2]), "r"(a[3]), "r"(b[0]), "r"(b[1]));
}
// int8 k32 MMAs, s32 accumulate. A-side signed (S-GEMM) or unsigned (PV).
__device__ __forceinline__ void mma_s8s8(int* d, const uint32_t* a, const uint32_t* b) {
    asm volatile(
        "mma.sync.aligned.m16n8k32.row.col.s32.s8.s8.s32 "
        "{%0,%1,%2,%3}, {%4,%5,%6,%7}, {%8,%9}, {%0,%1,%2,%3};"
        : "+r"(d[0]), "+r"(d[1]), "+r"(d[2]), "+r"(d[3])
        : "r"(a[0]), "r"(a[1]), "r"(a[2]), "r"(a[3]), "r"(b[0]), "r"(b[1]));
}
__device__ __forceinline__ void mma_u8s8(int* d, const uint32_t* a, const uint32_t* b) {
    asm volatile(
        "mma.sync.aligned.m16n8k32.row.col.s32.u8.s8.s32 "
        "{%0,%1,%2,%3}, {%4,%5,%6,%7}, {%8,%9}, {%0,%1,%2,%3};"
        : "+r"(d[0]), "+r"(d[1]), "+r"(d[2]), "+r"(d[3])
        : "r"(a[0]), "r"(a[1]), "r"(a[2]), "r"(a[3]), "r"(b[0]), "r"(b[1]));
}

__device__ __forceinline__ void split1(float f, __nv_bfloat16& h, __nv_bfloat16& l) {
    h = __float2bfloat16(f);
    l = __float2bfloat16(f - __bfloat162float(h));
}
__device__ __forceinline__ uint32_t pack2(__nv_bfloat16 a, __nv_bfloat16 b) {
    return ((uint32_t)*(uint16_t*)&b << 16) | *(uint16_t*)&a;
}
// signed nearest 2-digit split of fixed-point value (both digits s8)
__device__ __forceinline__ void qsplit(float v, int& hi, int& lo) {
    int qi = __float2int_rn(v * INV_LAM);
    qi = max(-32768, min(32639, qi));
    hi = (qi + 128) >> 8;            // [-128, 127]
    lo = qi - (hi << 8);             // [-128, 127]
}

// ---------------------------------------------------------------------------
// Scratch (device globals; allocation-free)
// ---------------------------------------------------------------------------
__device__ __align__(16) __nv_bfloat16 g_Ghi[(size_t)B_*T_*DG_],  g_Glo[(size_t)B_*T_*DG_];
__device__ __align__(16) __nv_bfloat16 g_Wqhi[(size_t)P_*DG_],    g_Wqlo[(size_t)P_*DG_];
__device__ __align__(16) __nv_bfloat16 g_Wkhi[(size_t)P_*DH_],    g_Wklo[(size_t)P_*DH_];
__device__ __align__(16) __nv_bfloat16 g_Hhi[(size_t)B_*L_*DH_],  g_Hlo[(size_t)B_*L_*DH_];
__device__ __align__(16) uint8_t g_Q8h[(size_t)B_*T_*P_],  g_Q8l[(size_t)B_*T_*P_];
__device__ __align__(16) uint8_t g_K8h[(size_t)B_*L_*P_],  g_K8l[(size_t)B_*L_*P_];
__device__ __align__(16) uint8_t g_P8h[(size_t)B_*T_*L_],  g_P8l[(size_t)B_*T_*L_];
__device__ __align__(16) uint8_t g_HT8h[(size_t)B_*DH_*L_], g_HT8l[(size_t)B_*DH_*L_];
__device__ float g_sum[(size_t)B_*T_];

// ---------------------------------------------------------------------------
// Elementwise fp32 -> bf16 hi/lo split
// ---------------------------------------------------------------------------
__global__ __launch_bounds__(256) void split_f32(
    const float* __restrict__ x, __nv_bfloat16* __restrict__ hi,
    __nv_bfloat16* __restrict__ lo, int n4)
{
    int i = blockIdx.x * 256 + threadIdx.x;
    if (i >= n4) return;
    float4 v = ((const float4*)x)[i];
    __nv_bfloat16 h0,h1,h2,h3,l0,l1,l2,l3;
    split1(v.x,h0,l0); split1(v.y,h1,l1); split1(v.z,h2,l2); split1(v.w,h3,l3);
    ((uint2*)hi)[i] = make_uint2(pack2(h0,h1), pack2(h2,h3));
    ((uint2*)lo)[i] = make_uint2(pack2(l0,l1), pack2(l2,l3));
}

__global__ __launch_bounds__(256) void zero_f32(float* __restrict__ p, int n) {
    int i = blockIdx.x * 256 + threadIdx.x;
    if (i < n) p[i] = 0.f;
}

// ---------------------------------------------------------------------------
// H [b, l, d] fp32 -> HT digit planes [b, d, l] s8 (transpose + quantize)
// ---------------------------------------------------------------------------
__global__ __launch_bounds__(256) void transpose_quant(
    const float* __restrict__ H, uint8_t* __restrict__ hi8, uint8_t* __restrict__ lo8)
{
    __shared__ float t[32][33];
    const int b  = blockIdx.z;
    const int l0 = blockIdx.y * 32;
    const int d0 = blockIdx.x * 32;
    const int tx = threadIdx.x, ty = threadIdx.y;
    const float* src = H + ((long)b * L_ + l0) * DH_ + d0;
#pragma unroll
    for (int r = 0; r < 4; r++)
        t[ty + 8*r][tx] = src[(long)(ty + 8*r) * DH_ + tx];
    __syncthreads();
#pragma unroll
    for (int r = 0; r < 4; r++) {
        float v = t[tx][ty + 8*r];
        int hi, lo; qsplit(v, hi, lo);
        long o = ((long)b * DH_ + d0 + ty + 8*r) * L_ + l0 + tx;
        hi8[o] = (uint8_t)(int8_t)hi;
        lo8[o] = (uint8_t)(int8_t)lo;
    }
}

// ---------------------------------------------------------------------------
// HMMA bf16 3-split NT GEMM (Q and K projections).
// BM=BN=128, BK=32, 8 warps, 2-stage cp.async, 2 CTAs/SM.
// Epilogue: quantize acc to s8 2-digit planes (hi, lo).
// ---------------------------------------------------------------------------
#define AROWB  80
#define TILEB  (128 * AROWB)
#define STAGEB (4 * TILEB)
#define GEMM_SMEM (2 * STAGEB)      // 81920

__global__ __launch_bounds__(256, 2) void gemm_bf16_q(
    const __nv_bfloat16* __restrict__ Ahi, const __nv_bfloat16* __restrict__ Alo,
    const __nv_bfloat16* __restrict__ Bhi, const __nv_bfloat16* __restrict__ Blo,
    uint8_t* __restrict__ Ch8, uint8_t* __restrict__ Cl8,
    int M, int N, int K)
{
    extern __shared__ char smem[];
    const uint32_t sb = smem_to_u32(smem);
    const int tid  = threadIdx.x, wid = tid >> 5, lane = tid & 31;
    const int row0 = blockIdx.y * 128;
    const int col0 = blockIdx.x * 128;
    const int wm = (wid >> 2) * 64;
    const int wn = (wid & 3) * 32;

    const char* gT[4] = {
        (const char*)(Ahi + (long)row0 * K), (const char*)(Alo + (long)row0 * K),
        (const char*)(Bhi + (long)col0 * K), (const char*)(Blo + (long)col0 * K) };
    const long ld = (long)K * 2;

    const int r_  = tid >> 2;
    const int cb_ = (tid & 3) * 16;
    const int NC  = K >> 5;

    auto load_stage = [&](int c) {
        const uint32_t s0 = sb + (uint32_t)((c & 1) * STAGEB);
        const long kb = (long)c * 64;
#pragma unroll
        for (int t = 0; t < 4; t++) {
            const char* g = gT[t] + kb;
#pragma unroll
            for (int i = 0; i < 2; i++) {
                const int row = r_ + i * 64;
                CP_ASYNC16(s0 + (uint32_t)(t * TILEB + row * AROWB + cb_),
                           g + (long)row * ld + cb_);
            }
        }
    };

    float acc[4][4][4];
#pragma unroll
    for (int a = 0; a < 4; a++)
#pragma unroll
        for (int b = 0; b < 4; b++)
#pragma unroll
            for (int q = 0; q < 4; q++) acc[a][b][q] = 0.f;

    load_stage(0); CP_COMMIT();
    load_stage(1); CP_COMMIT();

    const int aro = (wm + ((lane >> 3) & 1) * 8 + (lane & 7)) * AROWB + (lane >> 4) * 16;
    const int bro = (wn + (lane >> 4) * 8 + (lane & 7)) * AROWB + ((lane >> 3) & 1) * 16;

    for (int c = 0; c < NC; c++) {
        CP_WAIT1();
        __syncthreads();
        const uint32_t s0 = sb + (uint32_t)((c & 1) * STAGEB);

#pragma unroll
        for (int k16 = 0; k16 < 2; k16++) {
            const int kb = k16 * 32;
            uint32_t a_[4][4], bh[4][2], bl[4][2];
#pragma unroll
            for (int mt = 0; mt < 4; mt++)
                LDSM_X4(a_[mt][0], a_[mt][1], a_[mt][2], a_[mt][3],
                        s0 + (uint32_t)(aro + mt * (16 * AROWB) + kb));
#pragma unroll
            for (int p = 0; p < 2; p++) {
                LDSM_X4(bh[2*p][0], bh[2*p][1], bh[2*p+1][0], bh[2*p+1][1],
                        s0 + (uint32_t)(2 * TILEB + bro + p * (16 * AROWB) + kb));
                LDSM_X4(bl[2*p][0], bl[2*p][1], bl[2*p+1][0], bl[2*p+1][1],
                        s0 + (uint32_t)(3 * TILEB + bro + p * (16 * AROWB) + kb));
            }
#pragma unroll
            for (int mt = 0; mt < 4; mt++)
#pragma unroll
                for (int nt = 0; nt < 4; nt++)
                    mma16816(acc[mt][nt], a_[mt], bh[nt]);
#pragma unroll
            for (int mt = 0; mt < 4; mt++)
#pragma unroll
                for (int nt = 0; nt < 4; nt++)
                    mma16816(acc[mt][nt], a_[mt], bl[nt]);
#pragma unroll
            for (int mt = 0; mt < 4; mt++)
                LDSM_X4(a_[mt][0], a_[mt][1], a_[mt][2], a_[mt][3],
                        s0 + (uint32_t)(TILEB + aro + mt * (16 * AROWB) + kb));
#pragma unroll
            for (int mt = 0; mt < 4; mt++)
#pragma unroll
                for (int nt = 0; nt < 4; nt++)
                    mma16816(acc[mt][nt], a_[mt], bh[nt]);
        }
        __syncthreads();
        if (c + 2 < NC) load_stage(c + 2);
        CP_COMMIT();
    }

    // ---- epilogue: quantize to s8 digit planes ----
#pragma unroll
    for (int mt = 0; mt < 4; mt++) {
        const int rg0 = row0 + wm + mt * 16 + (lane >> 2);
#pragma unroll
        for (int nt = 0; nt < 4; nt++) {
            const int cg = col0 + wn + nt * 8 + (lane & 3) * 2;
            const float* d = acc[mt][nt];
            int h0,l0,h1,l1,h2,l2,h3,l3;
            qsplit(d[0], h0, l0); qsplit(d[1], h1, l1);
            qsplit(d[2], h2, l2); qsplit(d[3], h3, l3);
            const long o0 = (long)rg0 * N + cg;
            const long o1 = o0 + 8L * N;
            *(uint16_t*)(Ch8 + o0) = (uint16_t)((uint8_t)h0 | ((uint16_t)(uint8_t)h1 << 8));
            *(uint16_t*)(Cl8 + o0) = (uint16_t)((uint8_t)l0 | ((uint16_t)(uint8_t)l1 << 8));
            *(uint16_t*)(Ch8 + o1) = (uint16_t)((uint8_t)h2 | ((uint16_t)(uint8_t)h3 << 8));
            *(uint16_t*)(Cl8 + o1) = (uint16_t)((uint8_t)l2 | ((uint16_t)(uint8_t)l3 << 8));
        }
    }
}

// ---------------------------------------------------------------------------
// int8 two-digit NT GEMM:  acc = (Ahi*256+Alo) * (Bhi*256+Blo)^T, exact s32 digit
// accumulators (hh, mid, ll). CTA tile 128x64, BK=64 (s8), 8 warps (4M x 2N),
// warp tile 32x32, 2-stage cp.async.
// EPI 0 (S): p = exp(val*2^-28); quantize p (u8 digits); atomic row sums.
// EPI 1 (PV): out = val * 2^-24 / (rowdiv + eps), fp32.
// AUNS: A digits unsigned (PV); else signed (S).
// ---------------------------------------------------------------------------
#define S8_AT    (128 * AROWB)               // 10240
#define S8_BT    (64 * AROWB)                // 5120
#define S8_STAGE (2 * S8_AT + 2 * S8_BT)     // 30720
#define S8_SMEM  (2 * S8_STAGE)              // 61440

template<int EPI, bool AUNS>
__global__ __launch_bounds__(256, 1) void gemm_s8d(
    const uint8_t* __restrict__ Ahi, const uint8_t* __restrict__ Alo,
    const uint8_t* __restrict__ Bhi, const uint8_t* __restrict__ Blo,
    uint8_t* __restrict__ Ph8, uint8_t* __restrict__ Pl8,
    float* __restrict__ Cout, float* __restrict__ rowsums,
    const float* __restrict__ rowdiv,
    int N, int K, long sA, long sB, long sC, long sRS)
{
    extern __shared__ char smem[];
    const uint32_t sb = smem_to_u32(smem);
    const int tid  = threadIdx.x, wid = tid >> 5, lane = tid & 31;
    const int row0 = blockIdx.y * 128;
    const int col0 = blockIdx.x * 64;
    const long zb  = blockIdx.z;
    const int wm = (wid >> 1) * 32;
    const int wn = (wid & 1) * 32;

    const char* gAh = (const char*)(Ahi + zb * sA + (long)row0 * K);
    const char* gAl = (const char*)(Alo + zb * sA + (long)row0 * K);
    const char* gBh = (const char*)(Bhi + zb * sB + (long)col0 * K);
    const char* gBl = (const char*)(Blo + zb * sB + (long)col0 * K);

    const int r_  = tid >> 2;          // 0..63
    const int cb_ = (tid & 3) * 16;
    const int NC  = K >> 6;            // 64 s8 per chunk

    auto load_stage = [&](int c) {
        const uint32_t s0 = sb + (uint32_t)((c & 1) * S8_STAGE);
        const long kb = (long)c * 64;
#pragma unroll
        for (int i = 0; i < 2; i++) {
            const int row = r_ + i * 64;
            CP_ASYNC16(s0 + (uint32_t)(row * AROWB + cb_),
                       gAh + kb + (long)row * K + cb_);
            CP_ASYNC16(s0 + (uint32_t)(S8_AT + row * AROWB + cb_),
                       gAl + kb + (long)row * K + cb_);
        }
        CP_ASYNC16(s0 + (uint32_t)(2 * S8_AT + r_ * AROWB + cb_),
                   gBh + kb + (long)r_ * K + cb_);
        CP_ASYNC16(s0 + (uint32_t)(2 * S8_AT + S8_BT + r_ * AROWB + cb_),
                   gBl + kb + (long)r_ * K + cb_);
    };

    int hh[2][4][4], mid[2][4][4], ll[2][4][4];
#pragma unroll
    for (int a = 0; a < 2; a++)
#pragma unroll
        for (int b = 0; b < 4; b++)
#pragma unroll
            for (int q = 0; q < 4; q++) { hh[a][b][q] = 0; mid[a][b][q] = 0; ll[a][b][q] = 0; }

    load_stage(0); CP_COMMIT();
    load_stage(1); CP_COMMIT();

    const int aro = (wm + ((lane >> 3) & 1) * 8 + (lane & 7)) * AROWB + (lane >> 4) * 16;
    const int bro = (wn + (lane >> 4) * 8 + (lane & 7)) * AROWB + ((lane >> 3) & 1) * 16;

    for (int c = 0; c < NC; c++) {
        CP_WAIT1();
        __syncthreads();
        const uint32_t s0 = sb + (uint32_t)((c & 1) * S8_STAGE);

#pragma unroll
        for (int k32 = 0; k32 < 2; k32++) {
            const int kb = k32 * 32;
            uint32_t a_[2][4], bh[4][2], bl[4][2];
#pragma unroll
            for (int mt = 0; mt < 2; mt++)
                LDSM_X4(a_[mt][0], a_[mt][1], a_[mt][2], a_[mt][3],
                        s0 + (uint32_t)(aro + mt * (16 * AROWB) + kb));
#pragma unroll
            for (int p = 0; p < 2; p++) {
                LDSM_X4(bh[2*p][0], bh[2*p][1], bh[2*p+1][0], bh[2*p+1][1],
                        s0 + (uint32_t)(2 * S8_AT + bro + p * (16 * AROWB) + kb));
                LDSM_X4(bl[2*p][0], bl[2*p][1], bl[2*p+1][0], bl[2*p+1][1],
                        s0 + (uint32_t)(2 * S8_AT + S8_BT + bro + p * (16 * AROWB) + kb));
            }
#pragma unroll
            for (int mt = 0; mt < 2; mt++)
#pragma unroll
                for (int nt = 0; nt < 4; nt++) {
                    if (AUNS) mma_u8s8(hh[mt][nt],  a_[mt], bh[nt]);
                    else      mma_s8s8(hh[mt][nt],  a_[mt], bh[nt]);
                }
#pragma unroll
            for (int mt = 0; mt < 2; mt++)
#pragma unroll
                for (int nt = 0; nt < 4; nt++) {
                    if (AUNS) mma_u8s8(mid[mt][nt], a_[mt], bl[nt]);
                    else      mma_s8s8(mid[mt][nt], a_[mt], bl[nt]);
                }
#pragma unroll
            for (int mt = 0; mt < 2; mt++)
                LDSM_X4(a_[mt][0], a_[mt][1], a_[mt][2], a_[mt][3],
                        s0 + (uint32_t)(S8_AT + aro + mt * (16 * AROWB) + kb));
#pragma unroll
            for (int mt = 0; mt < 2; mt++)
#pragma unroll
                for (int nt = 0; nt < 4; nt++) {
                    if (AUNS) mma_u8s8(mid[mt][nt], a_[mt], bh[nt]);
                    else      mma_s8s8(mid[mt][nt], a_[mt], bh[nt]);
                }
#pragma unroll
            for (int mt = 0; mt < 2; mt++)
#pragma unroll
                for (int nt = 0; nt < 4; nt++) {
                    if (AUNS) mma_u8s8(ll[mt][nt],  a_[mt], bl[nt]);
                    else      mma_s8s8(ll[mt][nt],  a_[mt], bl[nt]);
                }
        }
        __syncthreads();
        if (c + 2 < NC) load_stage(c + 2);
        CP_COMMIT();
    }

    // ---- epilogue ----
    float* rowsum = (float*)smem;
    if (EPI == 0) {
        __syncthreads();
        if (tid < 128) rowsum[tid] = 0.f;
        __syncthreads();
    }

#pragma unroll
    for (int mt = 0; mt < 2; mt++) {
        const int rl0 = wm + mt * 16 + (lane >> 2);
        const int rg0 = row0 + rl0;
        float s0a = 0.f, s1a = 0.f;
        float m0 = 0.f, m1 = 0.f;
        if (EPI == 1) {
            m0 = SCALE_PV / (rowdiv[zb * sRS + rg0] + 1e-8f);
            m1 = SCALE_PV / (rowdiv[zb * sRS + rg0 + 8] + 1e-8f);
        }
#pragma unroll
        for (int nt = 0; nt < 4; nt++) {
            const int cg = col0 + wn + nt * 8 + (lane & 3) * 2;
            float v[4];
#pragma unroll
            for (int q = 0; q < 4; q++)
                v[q] = fmaf(65536.f, (float)hh[mt][nt][q],
                        fmaf(256.f, (float)mid[mt][nt][q], (float)ll[mt][nt][q]));
            if (EPI == 0) {
                int pi[4];
#pragma unroll
                for (int q = 0; q < 4; q++) {
                    float p = __expf(v[q] * SCALE_S);
                    pi[q] = min(max(__float2int_rn(p * INV_LAM), 0), 65535);
                }
                s0a += (float)(pi[0] + pi[1]) * LAM;
                s1a += (float)(pi[2] + pi[3]) * LAM;
                const long o0 = zb * sC + (long)rg0 * N + cg;
                const long o1 = o0 + 8L * N;
                *(uint16_t*)(Ph8 + o0) = (uint16_t)((pi[0] >> 8) | ((pi[1] >> 8) << 8));
                *(uint16_t*)(Pl8 + o0) = (uint16_t)((pi[0] & 255) | ((pi[1] & 255) << 8));
                *(uint16_t*)(Ph8 + o1) = (uint16_t)((pi[2] >> 8) | ((pi[3] >> 8) << 8));
                *(uint16_t*)(Pl8 + o1) = (uint16_t)((pi[2] & 255) | ((pi[3] & 255) << 8));
            } else {
                const long o0 = zb * sC + (long)rg0 * N + cg;
                const long o1 = o0 + 8L * N;
                *(float2*)(Cout + o0) = make_float2(v[0] * m0, v[1] * m0);
                *(float2*)(Cout + o1) = make_float2(v[2] * m1, v[3] * m1);
            }
        }
        if (EPI == 0) {
            s0a += __shfl_xor_sync(0xffffffffu, s0a, 1);
            s0a += __shfl_xor_sync(0xffffffffu, s0a, 2);
            s1a += __shfl_xor_sync(0xffffffffu, s1a, 1);
            s1a += __shfl_xor_sync(0xffffffffu, s1a, 2);
            if ((lane & 3) == 0) {
                atomicAdd(&rowsum[rl0],     s0a);
                atomicAdd(&rowsum[rl0 + 8], s1a);
            }
        }
    }
    if (EPI == 0) {
        __syncthreads();
        if (tid < 128)
            atomicAdd(&rowsums[zb * sRS + row0 + tid], rowsum[tid]);
    }
}

// ---------------------------------------------------------------------------
extern "C" void kernel_launch(void* const* d_in, const int* in_sizes, int n_in,
                              void* d_out, int out_size)
{
    const float* H  = (const float*)d_in[0];
    const float* G  = (const float*)d_in[1];
    const float* Wq = (const float*)d_in[2];
    const float* Wk = (const float*)d_in[3];
    float* Z = (float*)d_out;

    __nv_bfloat16 *Ghi,*Glo,*Wqhi,*Wqlo,*Wkhi,*Wklo,*Hhi,*Hlo;
    uint8_t *Q8h,*Q8l,*K8h,*K8l,*P8h,*P8l,*HT8h,*HT8l;
    float *sump;
    cudaGetSymbolAddress((void**)&Ghi, g_Ghi);   cudaGetSymbolAddress((void**)&Glo, g_Glo);
    cudaGetSymbolAddress((void**)&Wqhi,g_Wqhi);  cudaGetSymbolAddress((void**)&Wqlo,g_Wqlo);
    cudaGetSymbolAddress((void**)&Wkhi,g_Wkhi);  cudaGetSymbolAddress((void**)&Wklo,g_Wklo);
    cudaGetSymbolAddress((void**)&Hhi, g_Hhi);   cudaGetSymbolAddress((void**)&Hlo, g_Hlo);
    cudaGetSymbolAddress((void**)&Q8h, g_Q8h);   cudaGetSymbolAddress((void**)&Q8l, g_Q8l);
    cudaGetSymbolAddress((void**)&K8h, g_K8h);   cudaGetSymbolAddress((void**)&K8l, g_K8l);
    cudaGetSymbolAddress((void**)&P8h, g_P8h);   cudaGetSymbolAddress((void**)&P8l, g_P8l);
    cudaGetSymbolAddress((void**)&HT8h,g_HT8h);  cudaGetSymbolAddress((void**)&HT8l,g_HT8l);
    cudaGetSymbolAddress((void**)&sump,g_sum);

    cudaFuncSetAttribute(gemm_bf16_q, cudaFuncAttributeMaxDynamicSharedMemorySize, GEMM_SMEM);
    cudaFuncSetAttribute(gemm_s8d<0,false>, cudaFuncAttributeMaxDynamicSharedMemorySize, S8_SMEM);
    cudaFuncSetAttribute(gemm_s8d<1,true>,  cudaFuncAttributeMaxDynamicSharedMemorySize, S8_SMEM);

    // 1) prep: bf16 splits (G, Wq, Wk, H), H transpose+quantize, zero sums
    { int n4 = B_*T_*DG_/4;  split_f32<<<(n4+255)/256, 256>>>(G,  Ghi,  Glo,  n4); }
    { int n4 = P_*DG_/4;     split_f32<<<(n4+255)/256, 256>>>(Wq, Wqhi, Wqlo, n4); }
    { int n4 = P_*DH_/4;     split_f32<<<(n4+255)/256, 256>>>(Wk, Wkhi, Wklo, n4); }
    { int n4 = B_*L_*DH_/4;  split_f32<<<(n4+255)/256, 256>>>(H,  Hhi,  Hlo,  n4); }
    transpose_quant<<<dim3(DH_/32, L_/32, B_), dim3(32, 8)>>>(H, HT8h, HT8l);
    zero_f32<<<(B_*T_+255)/256, 256>>>(sump, B_*T_);

    // 2) Q = G*Wq^T -> s8 digit planes [8192, 256]
    gemm_bf16_q<<<dim3(P_/128, (B_*T_)/128, 1), 256, GEMM_SMEM>>>(
        Ghi, Glo, Wqhi, Wqlo, Q8h, Q8l, B_*T_, P_, DG_);

    // 3) K = H*Wk^T -> s8 digit planes [32768, 256]
    gemm_bf16_q<<<dim3(P_/128, (B_*L_)/128, 1), 256, GEMM_SMEM>>>(
        Hhi, Hlo, Wkhi, Wklo, K8h, K8l, B_*L_, P_, DH_);

    // 4) P = exp((QK^T)/16), quantized u8 digit planes + row sums
    gemm_s8d<0,false><<<dim3(L_/64, T_/128, B_), 256, S8_SMEM>>>(
        Q8h, Q8l, K8h, K8l, P8h, P8l, nullptr, sump, nullptr,
        L_, P_, (long)T_*P_, (long)L_*P_, (long)T_*L_, T_);

    // 5) Z = (P * H) / (s+eps)  via NT with HT digit planes
    gemm_s8d<1,true><<<dim3(DH_/64, T_/128, B_), 256, S8_SMEM>>>(
        P8h, P8l, HT8h, HT8l, nullptr, nullptr, Z, nullptr, sump,
        DH_, L_, (long)T_*L_, (long)DH_*L_, (long)T_*DH_, T_);
}

// round 12
// speedup vs baseline: 3.0799x; 3.0799x over previous
#include <cuda_runtime.h>
#include <cuda_fp16.h>
#include <cstdint>

// Problem: H[8,4096,1024] G[8,1024,768] Wq[256,768] Wk[256,1024] -> Z[8,1024,1024]
#define B_  8
#define L_  4096
#define DH_ 1024
#define T_  1024
#define DG_ 768
#define P_  256

// ---------------------------------------------------------------------------
// PTX helpers — base-target (sm_80+): mma.sync, ldmatrix, cp.async
// ---------------------------------------------------------------------------
__device__ __forceinline__ uint32_t smem_to_u32(const void* p) {
    uint32_t a;
    asm("{ .reg .u64 t; cvta.to.shared.u64 t, %1; cvt.u32.u64 %0, t; }" : "=r"(a) : "l"(p));
    return a;
}
#define CP_ASYNC16(sa, g) \
    asm volatile("cp.async.cg.shared.global [%0], [%1], 16;" :: "r"(sa), "l"(g))
#define CP_COMMIT() asm volatile("cp.async.commit_group;")
#define CP_WAIT1()  asm volatile("cp.async.wait_group 1;")

#define LDSM_X4(r0, r1, r2, r3, addr) \
    asm volatile("ldmatrix.sync.aligned.m8n8.x4.shared.b16 {%0,%1,%2,%3}, [%4];" \
                 : "=r"(r0), "=r"(r1), "=r"(r2), "=r"(r3) : "r"(addr))
#define LDSM_X4_T(r0, r1, r2, r3, addr) \
    asm volatile("ldmatrix.sync.aligned.m8n8.x4.trans.shared.b16 {%0,%1,%2,%3}, [%4];" \
                 : "=r"(r0), "=r"(r1), "=r"(r2), "=r"(r3) : "r"(addr))

// fp16 HMMA, fp32 accumulate
__device__ __forceinline__ void mma16816h(float* d, const uint32_t* a, const uint32_t* b) {
    asm volatile(
        "mma.sync.aligned.m16n8k16.row.col.f32.f16.f16.f32 "
        "{%0,%1,%2,%3}, {%4,%5,%6,%7}, {%8,%9}, {%0,%1,%2,%3};"
        : "+f"(d[0]), "+f"(d[1]), "+f"(d[2]), "+f"(d[3])
        : "r"(a[0]), "r"(a[1]), "r"(a[2]), "r"(a[3]), "r"(b[0]), "r"(b[1]));
}

__device__ __forceinline__ void splith(float f, __half& h, __half& l) {
    h = __float2half_rn(f);
    l = __float2half_rn(f - __half2float(h));
}
__device__ __forceinline__ uint32_t pack2h(__half a, __half b) {
    return ((uint32_t)*(uint16_t*)&b << 16) | *(uint16_t*)&a;
}

// ---------------------------------------------------------------------------
// Scratch (device globals; allocation-free)
// ---------------------------------------------------------------------------
__device__ __align__(16) __half g_Gh[(size_t)B_*T_*DG_];
__device__ __align__(16) __half g_Wqh[(size_t)P_*DG_],  g_Wql[(size_t)P_*DG_];
__device__ __align__(16) __half g_Wkh[(size_t)P_*DH_],  g_Wkl[(size_t)P_*DH_];
__device__ __align__(16) __half g_Hh[(size_t)B_*L_*DH_], g_Hl[(size_t)B_*L_*DH_];
__device__ __align__(16) __half g_Qh[(size_t)B_*T_*P_];
__device__ __align__(16) __half g_Kh[(size_t)B_*L_*P_],  g_Kl[(size_t)B_*L_*P_];
__device__ __align__(16) __half g_Ph[(size_t)B_*T_*L_],  g_Pl[(size_t)B_*T_*L_];
__device__ float g_sum[(size_t)B_*T_];

// ---------------------------------------------------------------------------
// fp32 -> fp16 single (hi only)
// ---------------------------------------------------------------------------
__global__ __launch_bounds__(256) void cvt16(
    const float* __restrict__ x, __half* __restrict__ hi, int n4)
{
    int i = blockIdx.x * 256 + threadIdx.x;
    if (i >= n4) return;
    float4 v = ((const float4*)x)[i];
    ((uint2*)hi)[i] = make_uint2(
        pack2h(__float2half_rn(v.x), __float2half_rn(v.y)),
        pack2h(__float2half_rn(v.z), __float2half_rn(v.w)));
}

// fp32 -> fp16 hi/lo split
__global__ __launch_bounds__(256) void split16(
    const float* __restrict__ x, __half* __restrict__ hi,
    __half* __restrict__ lo, int n4)
{
    int i = blockIdx.x * 256 + threadIdx.x;
    if (i >= n4) return;
    float4 v = ((const float4*)x)[i];
    __half h0,h1,h2,h3,l0,l1,l2,l3;
    splith(v.x,h0,l0); splith(v.y,h1,l1); splith(v.z,h2,l2); splith(v.w,h3,l3);
    ((uint2*)hi)[i] = make_uint2(pack2h(h0,h1), pack2h(h2,h3));
    ((uint2*)lo)[i] = make_uint2(pack2h(l0,l1), pack2h(l2,l3));
}

__global__ __launch_bounds__(256) void zero_f32(float* __restrict__ p, int n) {
    int i = blockIdx.x * 256 + threadIdx.x;
    if (i < n) p[i] = 0.f;
}

// ---------------------------------------------------------------------------
// fp16 2-term NT GEMM:  C[M,N] = A[M,K] * (Bhi+Blo)[N,K]^T
// BM=BN=128, BK=32, 8 warps (2M x 4N), 2-stage cp.async, 2 CTAs/SM.
// EPI 0: Ch = half(acc)             (Q projection)
// EPI 1: Ch/Cl = half-split(acc)    (K projection)
// EPI 3: p = exp(acc*scale); Ch/Cl = half-split(p); atomic row sums  (S)
// ---------------------------------------------------------------------------
#define AROWB  80
#define TILEB  (128 * AROWB)        // 10240 B per operand tile
#define T2_STAGE (3 * TILEB)        // A, Bh, Bl = 30720
#define T2_SMEM  (2 * T2_STAGE)     // 61440

template<int EPI>
__global__ __launch_bounds__(256, 2) void gemm_2t(
    const __half* __restrict__ A,
    const __half* __restrict__ Bhi, const __half* __restrict__ Blo,
    __half* __restrict__ Ch, __half* __restrict__ Cl,
    float* __restrict__ rowsums,
    int M, int N, int K, long sA, long sB, long sC, long sRS, float scale)
{
    extern __shared__ char smem[];
    const uint32_t sb = smem_to_u32(smem);
    const int tid  = threadIdx.x, wid = tid >> 5, lane = tid & 31;
    const int row0 = blockIdx.y * 128;
    const int col0 = blockIdx.x * 128;
    const long zb  = blockIdx.z;
    const int wm = (wid >> 2) * 64;
    const int wn = (wid & 3) * 32;

    const char* gT[3] = {
        (const char*)(A   + zb * sA + (long)row0 * K),
        (const char*)(Bhi + zb * sB + (long)col0 * K),
        (const char*)(Blo + zb * sB + (long)col0 * K) };
    const long ld = (long)K * 2;

    const int r_  = tid >> 2;
    const int cb_ = (tid & 3) * 16;
    const int NC  = K >> 5;

    auto load_stage = [&](int c) {
        const uint32_t s0 = sb + (uint32_t)((c & 1) * T2_STAGE);
        const long kb = (long)c * 64;
#pragma unroll
        for (int t = 0; t < 3; t++) {
            const char* g = gT[t] + kb;
#pragma unroll
            for (int i = 0; i < 2; i++) {
                const int row = r_ + i * 64;
                CP_ASYNC16(s0 + (uint32_t)(t * TILEB + row * AROWB + cb_),
                           g + (long)row * ld + cb_);
            }
        }
    };

    float acc[4][4][4];
#pragma unroll
    for (int a = 0; a < 4; a++)
#pragma unroll
        for (int b = 0; b < 4; b++)
#pragma unroll
            for (int q = 0; q < 4; q++) acc[a][b][q] = 0.f;

    load_stage(0); CP_COMMIT();
    load_stage(1); CP_COMMIT();

    const int aro = (wm + ((lane >> 3) & 1) * 8 + (lane & 7)) * AROWB + (lane >> 4) * 16;
    const int bro = (wn + (lane >> 4) * 8 + (lane & 7)) * AROWB + ((lane >> 3) & 1) * 16;

    for (int c = 0; c < NC; c++) {
        CP_WAIT1();
        __syncthreads();
        const uint32_t s0 = sb + (uint32_t)((c & 1) * T2_STAGE);

#pragma unroll
        for (int k16 = 0; k16 < 2; k16++) {
            const int kb = k16 * 32;
            uint32_t a_[4][4], bh[4][2], bl[4][2];
#pragma unroll
            for (int mt = 0; mt < 4; mt++)
                LDSM_X4(a_[mt][0], a_[mt][1], a_[mt][2], a_[mt][3],
                        s0 + (uint32_t)(aro + mt * (16 * AROWB) + kb));
#pragma unroll
            for (int p = 0; p < 2; p++) {
                LDSM_X4(bh[2*p][0], bh[2*p][1], bh[2*p+1][0], bh[2*p+1][1],
                        s0 + (uint32_t)(TILEB + bro + p * (16 * AROWB) + kb));
                LDSM_X4(bl[2*p][0], bl[2*p][1], bl[2*p+1][0], bl[2*p+1][1],
                        s0 + (uint32_t)(2 * TILEB + bro + p * (16 * AROWB) + kb));
            }
#pragma unroll
            for (int mt = 0; mt < 4; mt++)
#pragma unroll
                for (int nt = 0; nt < 4; nt++)
                    mma16816h(acc[mt][nt], a_[mt], bh[nt]);
#pragma unroll
            for (int mt = 0; mt < 4; mt++)
#pragma unroll
                for (int nt = 0; nt < 4; nt++)
                    mma16816h(acc[mt][nt], a_[mt], bl[nt]);
        }
        __syncthreads();
        if (c + 2 < NC) load_stage(c + 2);
        CP_COMMIT();
    }

    // ---- epilogue ----
    float* rowsum = (float*)smem;  // smem tiles dead now
    if (EPI == 3) {
        __syncthreads();
        if (tid < 128) rowsum[tid] = 0.f;
        __syncthreads();
    }

#pragma unroll
    for (int mt = 0; mt < 4; mt++) {
        const int rl0 = wm + mt * 16 + (lane >> 2);
        const int rg0 = row0 + rl0;
        float s0a = 0.f, s1a = 0.f;
#pragma unroll
        for (int nt = 0; nt < 4; nt++) {
            const int cg = col0 + wn + nt * 8 + (lane & 3) * 2;
            float* d = acc[mt][nt];
            float e0, e1, e2, e3;
            if (EPI == 3) {
                e0 = __expf(d[0] * scale); e1 = __expf(d[1] * scale);
                e2 = __expf(d[2] * scale); e3 = __expf(d[3] * scale);
                s0a += e0 + e1; s1a += e2 + e3;
            } else {
                e0 = d[0]; e1 = d[1]; e2 = d[2]; e3 = d[3];
            }
            const long o0 = zb * sC + (long)rg0 * N + cg;
            const long o1 = o0 + 8L * N;
            if (EPI == 0) {
                *(uint32_t*)(Ch + o0) = pack2h(__float2half_rn(e0), __float2half_rn(e1));
                *(uint32_t*)(Ch + o1) = pack2h(__float2half_rn(e2), __float2half_rn(e3));
            } else {
                __half h0,h1,h2,h3,l0,l1,l2,l3;
                splith(e0,h0,l0); splith(e1,h1,l1);
                splith(e2,h2,l2); splith(e3,h3,l3);
                *(uint32_t*)(Ch + o0) = pack2h(h0, h1);
                *(uint32_t*)(Cl + o0) = pack2h(l0, l1);
                *(uint32_t*)(Ch + o1) = pack2h(h2, h3);
                *(uint32_t*)(Cl + o1) = pack2h(l2, l3);
            }
        }
        if (EPI == 3) {
            s0a += __shfl_xor_sync(0xffffffffu, s0a, 1);
            s0a += __shfl_xor_sync(0xffffffffu, s0a, 2);
            s1a += __shfl_xor_sync(0xffffffffu, s1a, 1);
            s1a += __shfl_xor_sync(0xffffffffu, s1a, 2);
            if ((lane & 3) == 0) {
                atomicAdd(&rowsum[rl0],     s0a);
                atomicAdd(&rowsum[rl0 + 8], s1a);
            }
        }
    }
    if (EPI == 3) {
        __syncthreads();
        if (tid < 128)
            atomicAdd(&rowsums[zb * sRS + row0 + tid], rowsum[tid]);
    }
}

// ---------------------------------------------------------------------------
// PV GEMM (fp16 3-term, NN trans-B):
// Z[t,d] = (Σ_l (ph+pl)[t,l] * (hh+hl)[l,d]) / (s[t]+eps)
// BM=BN=128, BK=32, 8 warps, 2-stage cp.async, 2 CTAs/SM.
// ---------------------------------------------------------------------------
#define BROWB   272
#define BTILEB  (32 * BROWB)                 // 8704 B per B operand tile
#define PV_STAGE (2 * TILEB + 2 * BTILEB)    // 37888
#define PV_SMEM  (2 * PV_STAGE)              // 75776

__global__ __launch_bounds__(256, 2) void gemm_pv_nn(
    const __half* __restrict__ Ahi, const __half* __restrict__ Alo,
    const __half* __restrict__ Bhi, const __half* __restrict__ Blo,
    float* __restrict__ C, const float* __restrict__ rowdiv,
    int N, int K, long sA, long sB, long sC, long sDiv)
{
    extern __shared__ char smem[];
    const uint32_t sb = smem_to_u32(smem);
    const int tid  = threadIdx.x, wid = tid >> 5, lane = tid & 31;
    const int row0 = blockIdx.y * 128;
    const int col0 = blockIdx.x * 128;
    const long zb  = blockIdx.z;
    const int wm = (wid >> 2) * 64;
    const int wn = (wid & 3) * 32;

    const char* gAh = (const char*)(Ahi + zb * sA + (long)row0 * K);
    const char* gAl = (const char*)(Alo + zb * sA + (long)row0 * K);
    const char* gBh = (const char*)(Bhi + zb * sB + col0);
    const char* gBl = (const char*)(Blo + zb * sB + col0);
    const long ldA = (long)K * 2;
    const long ldB = (long)DH_ * 2;

    const int NC = K >> 5;

    const int ar_  = tid >> 2;
    const int acb_ = (tid & 3) * 16;
    const int br_  = tid >> 4;         // 0..15
    const int bcb_ = (tid & 15) * 16;  // 0..240

    auto load_stage = [&](int c) {
        const uint32_t s0 = sb + (uint32_t)((c & 1) * PV_STAGE);
        const long kbA = (long)c * 64;
        const long krB = (long)c * 32;
#pragma unroll
        for (int i = 0; i < 2; i++) {
            const int row = ar_ + i * 64;
            CP_ASYNC16(s0 + (uint32_t)(row * AROWB + acb_),
                       gAh + kbA + (long)row * ldA + acb_);
            CP_ASYNC16(s0 + (uint32_t)(TILEB + row * AROWB + acb_),
                       gAl + kbA + (long)row * ldA + acb_);
        }
#pragma unroll
        for (int i = 0; i < 2; i++) {
            const int krow = br_ + i * 16;
            CP_ASYNC16(s0 + (uint32_t)(2 * TILEB + krow * BROWB + bcb_),
                       gBh + (krB + krow) * ldB + bcb_);
            CP_ASYNC16(s0 + (uint32_t)(2 * TILEB + BTILEB + krow * BROWB + bcb_),
                       gBl + (krB + krow) * ldB + bcb_);
        }
    };

    float acc[4][4][4];
#pragma unroll
    for (int a = 0; a < 4; a++)
#pragma unroll
        for (int b = 0; b < 4; b++)
#pragma unroll
            for (int q = 0; q < 4; q++) acc[a][b][q] = 0.f;

    load_stage(0); CP_COMMIT();
    load_stage(1); CP_COMMIT();

    const int aro = (wm + ((lane >> 3) & 1) * 8 + (lane & 7)) * AROWB + (lane >> 4) * 16;
    const int btm = lane >> 3;
    const int bkr = (lane & 7) + (btm & 1) * 8;
    const int bco = (wn + (btm >> 1) * 8) * 2;

    for (int c = 0; c < NC; c++) {
        CP_WAIT1();
        __syncthreads();
        const uint32_t s0 = sb + (uint32_t)((c & 1) * PV_STAGE);

#pragma unroll
        for (int k16 = 0; k16 < 2; k16++) {
            const int kbA = k16 * 32;
            uint32_t a_[4][4], bh[4][2], bl[4][2];
#pragma unroll
            for (int mt = 0; mt < 4; mt++)
                LDSM_X4(a_[mt][0], a_[mt][1], a_[mt][2], a_[mt][3],
                        s0 + (uint32_t)(aro + mt * (16 * AROWB) + kbA));
            const uint32_t bbase = s0 + (uint32_t)(2 * TILEB + (k16 * 16 + bkr) * BROWB + bco);
#pragma unroll
            for (int p = 0; p < 2; p++) {
                LDSM_X4_T(bh[2*p][0], bh[2*p][1], bh[2*p+1][0], bh[2*p+1][1],
                          bbase + (uint32_t)(p * 32));
                LDSM_X4_T(bl[2*p][0], bl[2*p][1], bl[2*p+1][0], bl[2*p+1][1],
                          bbase + (uint32_t)(BTILEB + p * 32));
            }
#pragma unroll
            for (int mt = 0; mt < 4; mt++)
#pragma unroll
                for (int nt = 0; nt < 4; nt++)
                    mma16816h(acc[mt][nt], a_[mt], bh[nt]);
#pragma unroll
            for (int mt = 0; mt < 4; mt++)
#pragma unroll
                for (int nt = 0; nt < 4; nt++)
                    mma16816h(acc[mt][nt], a_[mt], bl[nt]);
#pragma unroll
            for (int mt = 0; mt < 4; mt++)
                LDSM_X4(a_[mt][0], a_[mt][1], a_[mt][2], a_[mt][3],
                        s0 + (uint32_t)(TILEB + aro + mt * (16 * AROWB) + kbA));
#pragma unroll
            for (int mt = 0; mt < 4; mt++)
#pragma unroll
                for (int nt = 0; nt < 4; nt++)
                    mma16816h(acc[mt][nt], a_[mt], bh[nt]);
        }
        __syncthreads();
        if (c + 2 < NC) load_stage(c + 2);
        CP_COMMIT();
    }

    // ---- epilogue: divide by row sum ----
#pragma unroll
    for (int mt = 0; mt < 4; mt++) {
        const int rg0 = row0 + wm + mt * 16 + (lane >> 2);
        const int rg1 = rg0 + 8;
        const float m0 = 1.f / (rowdiv[zb * sDiv + rg0] + 1e-8f);
        const float m1 = 1.f / (rowdiv[zb * sDiv + rg1] + 1e-8f);
#pragma unroll
        for (int nt = 0; nt < 4; nt++) {
            const int cg = col0 + wn + nt * 8 + (lane & 3) * 2;
            const float* d = acc[mt][nt];
            *(float2*)(C + zb * sC + (long)rg0 * N + cg) = make_float2(d[0]*m0, d[1]*m0);
            *(float2*)(C + zb * sC + (long)rg1 * N + cg) = make_float2(d[2]*m1, d[3]*m1);
        }
    }
}

// ---------------------------------------------------------------------------
extern "C" void kernel_launch(void* const* d_in, const int* in_sizes, int n_in,
                              void* d_out, int out_size)
{
    const float* H  = (const float*)d_in[0];
    const float* G  = (const float*)d_in[1];
    const float* Wq = (const float*)d_in[2];
    const float* Wk = (const float*)d_in[3];
    float* Z = (float*)d_out;

    __half *Gh,*Wqh,*Wql,*Wkh,*Wkl,*Hh,*Hl,*Qh,*Kh,*Kl,*Ph,*Pl;
    float *sump;
    cudaGetSymbolAddress((void**)&Gh,  g_Gh);
    cudaGetSymbolAddress((void**)&Wqh, g_Wqh);  cudaGetSymbolAddress((void**)&Wql, g_Wql);
    cudaGetSymbolAddress((void**)&Wkh, g_Wkh);  cudaGetSymbolAddress((void**)&Wkl, g_Wkl);
    cudaGetSymbolAddress((void**)&Hh,  g_Hh);   cudaGetSymbolAddress((void**)&Hl,  g_Hl);
    cudaGetSymbolAddress((void**)&Qh,  g_Qh);
    cudaGetSymbolAddress((void**)&Kh,  g_Kh);   cudaGetSymbolAddress((void**)&Kl,  g_Kl);
    cudaGetSymbolAddress((void**)&Ph,  g_Ph);   cudaGetSymbolAddress((void**)&Pl,  g_Pl);
    cudaGetSymbolAddress((void**)&sump,g_sum);

    cudaFuncSetAttribute(gemm_2t<0>, cudaFuncAttributeMaxDynamicSharedMemorySize, T2_SMEM);
    cudaFuncSetAttribute(gemm_2t<1>, cudaFuncAttributeMaxDynamicSharedMemorySize, T2_SMEM);
    cudaFuncSetAttribute(gemm_2t<3>, cudaFuncAttributeMaxDynamicSharedMemorySize, T2_SMEM);
    cudaFuncSetAttribute(gemm_pv_nn, cudaFuncAttributeMaxDynamicSharedMemorySize, PV_SMEM);

    // 1) fp16 conversions + zero row sums
    { int n4 = B_*T_*DG_/4;  cvt16  <<<(n4+255)/256, 256>>>(G,  Gh,  n4); }
    { int n4 = P_*DG_/4;     split16<<<(n4+255)/256, 256>>>(Wq, Wqh, Wql, n4); }
    { int n4 = P_*DH_/4;     split16<<<(n4+255)/256, 256>>>(Wk, Wkh, Wkl, n4); }
    { int n4 = B_*L_*DH_/4;  split16<<<(n4+255)/256, 256>>>(H,  Hh,  Hl,  n4); }
    zero_f32<<<(B_*T_+255)/256, 256>>>(sump, B_*T_);

    // 2) Q = Gh * (Wqh+Wql)^T -> Qh single fp16 [8192,256]
    gemm_2t<0><<<dim3(P_/128, (B_*T_)/128, 1), 256, T2_SMEM>>>(
        Gh, Wqh, Wql, Qh, nullptr, nullptr,
        B_*T_, P_, DG_, 0, 0, 0, 0, 1.f);

    // 3) K = Hh * (Wkh+Wkl)^T -> K hi/lo fp16 [32768,256]
    gemm_2t<1><<<dim3(P_/128, (B_*L_)/128, 1), 256, T2_SMEM>>>(
        Hh, Wkh, Wkl, Kh, Kl, nullptr,
        B_*L_, P_, DH_, 0, 0, 0, 0, 1.f);

    // 4) P = exp((Qh*(Kh+Kl)^T)/16) hi/lo fp16 + row sums
    gemm_2t<3><<<dim3(L_/128, T_/128, B_), 256, T2_SMEM>>>(
        Qh, Kh, Kl, Ph, Pl, sump,
        T_, L_, P_, (long)T_*P_, (long)L_*P_, (long)T_*L_, T_, 0.0625f);

    // 5) Z = ((Ph+Pl) * (Hh+Hl)) / (s+eps)   (NN, trans-B reads H directly)
    gemm_pv_nn<<<dim3(DH_/128, T_/128, B_), 256, PV_SMEM>>>(
        Ph, Pl, Hh, Hl, Z, sump,
        DH_, L_, (long)T_*L_, (long)L_*DH_, (long)T_*DH_, T_);
}

// round 13
// speedup vs baseline: 4.0056x; 1.3005x over previous
#include <cuda_runtime.h>
#include <cuda_fp16.h>
#include <cstdint>

// Problem: H[8,4096,1024] G[8,1024,768] Wq[256,768] Wk[256,1024] -> Z[8,1024,1024]
#define B_  8
#define L_  4096
#define DH_ 1024
#define T_  1024
#define DG_ 768
#define P_  256

// ---------------------------------------------------------------------------
// PTX helpers — base-target (sm_80+): mma.sync, ldmatrix, cp.async
// ---------------------------------------------------------------------------
__device__ __forceinline__ uint32_t smem_to_u32(const void* p) {
    uint32_t a;
    asm("{ .reg .u64 t; cvta.to.shared.u64 t, %1; cvt.u32.u64 %0, t; }" : "=r"(a) : "l"(p));
    return a;
}
#define CP_ASYNC16(sa, g) \
    asm volatile("cp.async.cg.shared.global [%0], [%1], 16;" :: "r"(sa), "l"(g))
#define CP_COMMIT() asm volatile("cp.async.commit_group;")
#define CP_WAIT1()  asm volatile("cp.async.wait_group 1;")

#define LDSM_X4(r0, r1, r2, r3, addr) \
    asm volatile("ldmatrix.sync.aligned.m8n8.x4.shared.b16 {%0,%1,%2,%3}, [%4];" \
                 : "=r"(r0), "=r"(r1), "=r"(r2), "=r"(r3) : "r"(addr))
#define LDSM_X4_T(r0, r1, r2, r3, addr) \
    asm volatile("ldmatrix.sync.aligned.m8n8.x4.trans.shared.b16 {%0,%1,%2,%3}, [%4];" \
                 : "=r"(r0), "=r"(r1), "=r"(r2), "=r"(r3) : "r"(addr))

// fp16 HMMA, fp32 accumulate
__device__ __forceinline__ void mma16816h(float* d, const uint32_t* a, const uint32_t* b) {
    asm volatile(
        "mma.sync.aligned.m16n8k16.row.col.f32.f16.f16.f32 "
        "{%0,%1,%2,%3}, {%4,%5,%6,%7}, {%8,%9}, {%0,%1,%2,%3};"
        : "+f"(d[0]), "+f"(d[1]), "+f"(d[2]), "+f"(d[3])
        : "r"(a[0]), "r"(a[1]), "r"(a[2]), "r"(a[3]), "r"(b[0]), "r"(b[1]));
}

__device__ __forceinline__ void splith(float f, __half& h, __half& l) {
    h = __float2half_rn(f);
    l = __float2half_rn(f - __half2float(h));
}
__device__ __forceinline__ uint32_t pack2h(__half a, __half b) {
    return ((uint32_t)*(uint16_t*)&b << 16) | *(uint16_t*)&a;
}

// ---------------------------------------------------------------------------
// Scratch (device globals; allocation-free)
// ---------------------------------------------------------------------------
__device__ __align__(16) __half g_Gh[(size_t)B_*T_*DG_];
__device__ __align__(16) __half g_Wqh[(size_t)P_*DG_],  g_Wql[(size_t)P_*DG_];
__device__ __align__(16) __half g_Wkh[(size_t)P_*DH_],  g_Wkl[(size_t)P_*DH_];
__device__ __align__(16) __half g_Hh[(size_t)B_*L_*DH_], g_Hl[(size_t)B_*L_*DH_];
__device__ __align__(16) __half g_Qh[(size_t)B_*T_*P_];
__device__ __align__(16) __half g_Kh[(size_t)B_*L_*P_],  g_Kl[(size_t)B_*L_*P_];
__device__ __align__(16) __half g_Ph[(size_t)B_*T_*L_];
__device__ float g_sum[(size_t)B_*T_];

// ---------------------------------------------------------------------------
// fp32 -> fp16 single (hi only)
// ---------------------------------------------------------------------------
__global__ __launch_bounds__(256) void cvt16(
    const float* __restrict__ x, __half* __restrict__ hi, int n4)
{
    int i = blockIdx.x * 256 + threadIdx.x;
    if (i >= n4) return;
    float4 v = ((const float4*)x)[i];
    ((uint2*)hi)[i] = make_uint2(
        pack2h(__float2half_rn(v.x), __float2half_rn(v.y)),
        pack2h(__float2half_rn(v.z), __float2half_rn(v.w)));
}

// fp32 -> fp16 hi/lo split
__global__ __launch_bounds__(256) void split16(
    const float* __restrict__ x, __half* __restrict__ hi,
    __half* __restrict__ lo, int n4)
{
    int i = blockIdx.x * 256 + threadIdx.x;
    if (i >= n4) return;
    float4 v = ((const float4*)x)[i];
    __half h0,h1,h2,h3,l0,l1,l2,l3;
    splith(v.x,h0,l0); splith(v.y,h1,l1); splith(v.z,h2,l2); splith(v.w,h3,l3);
    ((uint2*)hi)[i] = make_uint2(pack2h(h0,h1), pack2h(h2,h3));
    ((uint2*)lo)[i] = make_uint2(pack2h(l0,l1), pack2h(l2,l3));
}

__global__ __launch_bounds__(256) void zero_f32(float* __restrict__ p, int n) {
    int i = blockIdx.x * 256 + threadIdx.x;
    if (i < n) p[i] = 0.f;
}

// ---------------------------------------------------------------------------
// fp16 2-term NT GEMM:  C[M,N] = A[M,K] * (Bhi+Blo)[N,K]^T
// BM=BN=128, BK=32, 8 warps (2M x 4N), 2-stage cp.async, 2 CTAs/SM.
// EPI 0: Ch = half(acc)             (Q projection)
// EPI 1: Ch/Cl = half-split(acc)    (K projection)
// EPI 3: ph = half(exp(acc*scale)); Ch = ph; row sums accumulate float(ph)
//        (sums over the ROUNDED weights -> PV normalizer is exactly consistent)
// ---------------------------------------------------------------------------
#define AROWB  80
#define TILEB  (128 * AROWB)        // 10240 B per operand tile
#define T2_STAGE (3 * TILEB)        // A, Bh, Bl = 30720
#define T2_SMEM  (2 * T2_STAGE)     // 61440

template<int EPI>
__global__ __launch_bounds__(256, 2) void gemm_2t(
    const __half* __restrict__ A,
    const __half* __restrict__ Bhi, const __half* __restrict__ Blo,
    __half* __restrict__ Ch, __half* __restrict__ Cl,
    float* __restrict__ rowsums,
    int M, int N, int K, long sA, long sB, long sC, long sRS, float scale)
{
    extern __shared__ char smem[];
    const uint32_t sb = smem_to_u32(smem);
    const int tid  = threadIdx.x, wid = tid >> 5, lane = tid & 31;
    const int row0 = blockIdx.y * 128;
    const int col0 = blockIdx.x * 128;
    const long zb  = blockIdx.z;
    const int wm = (wid >> 2) * 64;
    const int wn = (wid & 3) * 32;

    const char* gT[3] = {
        (const char*)(A   + zb * sA + (long)row0 * K),
        (const char*)(Bhi + zb * sB + (long)col0 * K),
        (const char*)(Blo + zb * sB + (long)col0 * K) };
    const long ld = (long)K * 2;

    const int r_  = tid >> 2;
    const int cb_ = (tid & 3) * 16;
    const int NC  = K >> 5;

    auto load_stage = [&](int c) {
        const uint32_t s0 = sb + (uint32_t)((c & 1) * T2_STAGE);
        const long kb = (long)c * 64;
#pragma unroll
        for (int t = 0; t < 3; t++) {
            const char* g = gT[t] + kb;
#pragma unroll
            for (int i = 0; i < 2; i++) {
                const int row = r_ + i * 64;
                CP_ASYNC16(s0 + (uint32_t)(t * TILEB + row * AROWB + cb_),
                           g + (long)row * ld + cb_);
            }
        }
    };

    float acc[4][4][4];
#pragma unroll
    for (int a = 0; a < 4; a++)
#pragma unroll
        for (int b = 0; b < 4; b++)
#pragma unroll
            for (int q = 0; q < 4; q++) acc[a][b][q] = 0.f;

    load_stage(0); CP_COMMIT();
    load_stage(1); CP_COMMIT();

    const int aro = (wm + ((lane >> 3) & 1) * 8 + (lane & 7)) * AROWB + (lane >> 4) * 16;
    const int bro = (wn + (lane >> 4) * 8 + (lane & 7)) * AROWB + ((lane >> 3) & 1) * 16;

    for (int c = 0; c < NC; c++) {
        CP_WAIT1();
        __syncthreads();
        const uint32_t s0 = sb + (uint32_t)((c & 1) * T2_STAGE);

#pragma unroll
        for (int k16 = 0; k16 < 2; k16++) {
            const int kb = k16 * 32;
            uint32_t a_[4][4], bh[4][2], bl[4][2];
#pragma unroll
            for (int mt = 0; mt < 4; mt++)
                LDSM_X4(a_[mt][0], a_[mt][1], a_[mt][2], a_[mt][3],
                        s0 + (uint32_t)(aro + mt * (16 * AROWB) + kb));
#pragma unroll
            for (int p = 0; p < 2; p++) {
                LDSM_X4(bh[2*p][0], bh[2*p][1], bh[2*p+1][0], bh[2*p+1][1],
                        s0 + (uint32_t)(TILEB + bro + p * (16 * AROWB) + kb));
                LDSM_X4(bl[2*p][0], bl[2*p][1], bl[2*p+1][0], bl[2*p+1][1],
                        s0 + (uint32_t)(2 * TILEB + bro + p * (16 * AROWB) + kb));
            }
#pragma unroll
            for (int mt = 0; mt < 4; mt++)
#pragma unroll
                for (int nt = 0; nt < 4; nt++)
                    mma16816h(acc[mt][nt], a_[mt], bh[nt]);
#pragma unroll
            for (int mt = 0; mt < 4; mt++)
#pragma unroll
                for (int nt = 0; nt < 4; nt++)
                    mma16816h(acc[mt][nt], a_[mt], bl[nt]);
        }
        __syncthreads();
        if (c + 2 < NC) load_stage(c + 2);
        CP_COMMIT();
    }

    // ---- epilogue ----
    float* rowsum = (float*)smem;  // smem tiles dead now
    if (EPI == 3) {
        __syncthreads();
        if (tid < 128) rowsum[tid] = 0.f;
        __syncthreads();
    }

#pragma unroll
    for (int mt = 0; mt < 4; mt++) {
        const int rl0 = wm + mt * 16 + (lane >> 2);
        const int rg0 = row0 + rl0;
        float s0a = 0.f, s1a = 0.f;
#pragma unroll
        for (int nt = 0; nt < 4; nt++) {
            const int cg = col0 + wn + nt * 8 + (lane & 3) * 2;
            float* d = acc[mt][nt];
            const long o0 = zb * sC + (long)rg0 * N + cg;
            const long o1 = o0 + 8L * N;
            if (EPI == 3) {
                __half p0 = __float2half_rn(__expf(d[0] * scale));
                __half p1 = __float2half_rn(__expf(d[1] * scale));
                __half p2 = __float2half_rn(__expf(d[2] * scale));
                __half p3 = __float2half_rn(__expf(d[3] * scale));
                s0a += __half2float(p0) + __half2float(p1);
                s1a += __half2float(p2) + __half2float(p3);
                *(uint32_t*)(Ch + o0) = pack2h(p0, p1);
                *(uint32_t*)(Ch + o1) = pack2h(p2, p3);
            } else if (EPI == 0) {
                *(uint32_t*)(Ch + o0) = pack2h(__float2half_rn(d[0]), __float2half_rn(d[1]));
                *(uint32_t*)(Ch + o1) = pack2h(__float2half_rn(d[2]), __float2half_rn(d[3]));
            } else {
                __half h0,h1,h2,h3,l0,l1,l2,l3;
                splith(d[0],h0,l0); splith(d[1],h1,l1);
                splith(d[2],h2,l2); splith(d[3],h3,l3);
                *(uint32_t*)(Ch + o0) = pack2h(h0, h1);
                *(uint32_t*)(Cl + o0) = pack2h(l0, l1);
                *(uint32_t*)(Ch + o1) = pack2h(h2, h3);
                *(uint32_t*)(Cl + o1) = pack2h(l2, l3);
            }
        }
        if (EPI == 3) {
            s0a += __shfl_xor_sync(0xffffffffu, s0a, 1);
            s0a += __shfl_xor_sync(0xffffffffu, s0a, 2);
            s1a += __shfl_xor_sync(0xffffffffu, s1a, 1);
            s1a += __shfl_xor_sync(0xffffffffu, s1a, 2);
            if ((lane & 3) == 0) {
                atomicAdd(&rowsum[rl0],     s0a);
                atomicAdd(&rowsum[rl0 + 8], s1a);
            }
        }
    }
    if (EPI == 3) {
        __syncthreads();
        if (tid < 128)
            atomicAdd(&rowsums[zb * sRS + row0 + tid], rowsum[tid]);
    }
}

// ---------------------------------------------------------------------------
// PV GEMM (fp16 2-term, NN trans-B):
// Z[t,d] = (Σ_l Ph[t,l] * (hh+hl)[l,d]) / (s[t]+eps),  s = Σ_l Ph[t,l]
// BM=BN=128, BK=32, 8 warps, 2-stage cp.async, 2 CTAs/SM.
// ---------------------------------------------------------------------------
#define BROWB   272
#define BTILEB  (32 * BROWB)                 // 8704 B per B operand tile
#define PV_STAGE (TILEB + 2 * BTILEB)        // 27648
#define PV_SMEM  (2 * PV_STAGE)              // 55296

__global__ __launch_bounds__(256, 2) void gemm_pv_nn(
    const __half* __restrict__ Ah,
    const __half* __restrict__ Bhi, const __half* __restrict__ Blo,
    float* __restrict__ C, const float* __restrict__ rowdiv,
    int N, int K, long sA, long sB, long sC, long sDiv)
{
    extern __shared__ char smem[];
    const uint32_t sb = smem_to_u32(smem);
    const int tid  = threadIdx.x, wid = tid >> 5, lane = tid & 31;
    const int row0 = blockIdx.y * 128;
    const int col0 = blockIdx.x * 128;
    const long zb  = blockIdx.z;
    const int wm = (wid >> 2) * 64;
    const int wn = (wid & 3) * 32;

    const char* gAh = (const char*)(Ah  + zb * sA + (long)row0 * K);
    const char* gBh = (const char*)(Bhi + zb * sB + col0);
    const char* gBl = (const char*)(Blo + zb * sB + col0);
    const long ldA = (long)K * 2;
    const long ldB = (long)DH_ * 2;

    const int NC = K >> 5;

    const int ar_  = tid >> 2;
    const int acb_ = (tid & 3) * 16;
    const int br_  = tid >> 4;         // 0..15
    const int bcb_ = (tid & 15) * 16;  // 0..240

    auto load_stage = [&](int c) {
        const uint32_t s0 = sb + (uint32_t)((c & 1) * PV_STAGE);
        const long kbA = (long)c * 64;
        const long krB = (long)c * 32;
#pragma unroll
        for (int i = 0; i < 2; i++) {
            const int row = ar_ + i * 64;
            CP_ASYNC16(s0 + (uint32_t)(row * AROWB + acb_),
                       gAh + kbA + (long)row * ldA + acb_);
        }
#pragma unroll
        for (int i = 0; i < 2; i++) {
            const int krow = br_ + i * 16;
            CP_ASYNC16(s0 + (uint32_t)(TILEB + krow * BROWB + bcb_),
                       gBh + (krB + krow) * ldB + bcb_);
            CP_ASYNC16(s0 + (uint32_t)(TILEB + BTILEB + krow * BROWB + bcb_),
                       gBl + (krB + krow) * ldB + bcb_);
        }
    };

    float acc[4][4][4];
#pragma unroll
    for (int a = 0; a < 4; a++)
#pragma unroll
        for (int b = 0; b < 4; b++)
#pragma unroll
            for (int q = 0; q < 4; q++) acc[a][b][q] = 0.f;

    load_stage(0); CP_COMMIT();
    load_stage(1); CP_COMMIT();

    const int aro = (wm + ((lane >> 3) & 1) * 8 + (lane & 7)) * AROWB + (lane >> 4) * 16;
    const int btm = lane >> 3;
    const int bkr = (lane & 7) + (btm & 1) * 8;
    const int bco = (wn + (btm >> 1) * 8) * 2;

    for (int c = 0; c < NC; c++) {
        CP_WAIT1();
        __syncthreads();
        const uint32_t s0 = sb + (uint32_t)((c & 1) * PV_STAGE);

#pragma unroll
        for (int k16 = 0; k16 < 2; k16++) {
            const int kbA = k16 * 32;
            uint32_t a_[4][4], bh[4][2], bl[4][2];
#pragma unroll
            for (int mt = 0; mt < 4; mt++)
                LDSM_X4(a_[mt][0], a_[mt][1], a_[mt][2], a_[mt][3],
                        s0 + (uint32_t)(aro + mt * (16 * AROWB) + kbA));
            const uint32_t bbase = s0 + (uint32_t)(TILEB + (k16 * 16 + bkr) * BROWB + bco);
#pragma unroll
            for (int p = 0; p < 2; p++) {
                LDSM_X4_T(bh[2*p][0], bh[2*p][1], bh[2*p+1][0], bh[2*p+1][1],
                          bbase + (uint32_t)(p * 32));
                LDSM_X4_T(bl[2*p][0], bl[2*p][1], bl[2*p+1][0], bl[2*p+1][1],
                          bbase + (uint32_t)(BTILEB + p * 32));
            }
#pragma unroll
            for (int mt = 0; mt < 4; mt++)
#pragma unroll
                for (int nt = 0; nt < 4; nt++)
                    mma16816h(acc[mt][nt], a_[mt], bh[nt]);
#pragma unroll
            for (int mt = 0; mt < 4; mt++)
#pragma unroll
                for (int nt = 0; nt < 4; nt++)
                    mma16816h(acc[mt][nt], a_[mt], bl[nt]);
        }
        __syncthreads();
        if (c + 2 < NC) load_stage(c + 2);
        CP_COMMIT();
    }

    // ---- epilogue: divide by row sum ----
#pragma unroll
    for (int mt = 0; mt < 4; mt++) {
        const int rg0 = row0 + wm + mt * 16 + (lane >> 2);
        const int rg1 = rg0 + 8;
        const float m0 = 1.f / (rowdiv[zb * sDiv + rg0] + 1e-8f);
        const float m1 = 1.f / (rowdiv[zb * sDiv + rg1] + 1e-8f);
#pragma unroll
        for (int nt = 0; nt < 4; nt++) {
            const int cg = col0 + wn + nt * 8 + (lane & 3) * 2;
            const float* d = acc[mt][nt];
            *(float2*)(C + zb * sC + (long)rg0 * N + cg) = make_float2(d[0]*m0, d[1]*m0);
            *(float2*)(C + zb * sC + (long)rg1 * N + cg) = make_float2(d[2]*m1, d[3]*m1);
        }
    }
}

// ---------------------------------------------------------------------------
extern "C" void kernel_launch(void* const* d_in, const int* in_sizes, int n_in,
                              void* d_out, int out_size)
{
    const float* H  = (const float*)d_in[0];
    const float* G  = (const float*)d_in[1];
    const float* Wq = (const float*)d_in[2];
    const float* Wk = (const float*)d_in[3];
    float* Z = (float*)d_out;

    __half *Gh,*Wqh,*Wql,*Wkh,*Wkl,*Hh,*Hl,*Qh,*Kh,*Kl,*Ph;
    float *sump;
    cudaGetSymbolAddress((void**)&Gh,  g_Gh);
    cudaGetSymbolAddress((void**)&Wqh, g_Wqh);  cudaGetSymbolAddress((void**)&Wql, g_Wql);
    cudaGetSymbolAddress((void**)&Wkh, g_Wkh);  cudaGetSymbolAddress((void**)&Wkl, g_Wkl);
    cudaGetSymbolAddress((void**)&Hh,  g_Hh);   cudaGetSymbolAddress((void**)&Hl,  g_Hl);
    cudaGetSymbolAddress((void**)&Qh,  g_Qh);
    cudaGetSymbolAddress((void**)&Kh,  g_Kh);   cudaGetSymbolAddress((void**)&Kl,  g_Kl);
    cudaGetSymbolAddress((void**)&Ph,  g_Ph);
    cudaGetSymbolAddress((void**)&sump,g_sum);

    cudaFuncSetAttribute(gemm_2t<0>, cudaFuncAttributeMaxDynamicSharedMemorySize, T2_SMEM);
    cudaFuncSetAttribute(gemm_2t<1>, cudaFuncAttributeMaxDynamicSharedMemorySize, T2_SMEM);
    cudaFuncSetAttribute(gemm_2t<3>, cudaFuncAttributeMaxDynamicSharedMemorySize, T2_SMEM);
    cudaFuncSetAttribute(gemm_pv_nn, cudaFuncAttributeMaxDynamicSharedMemorySize, PV_SMEM);

    // 1) fp16 conversions + zero row sums
    { int n4 = B_*T_*DG_/4;  cvt16  <<<(n4+255)/256, 256>>>(G,  Gh,  n4); }
    { int n4 = P_*DG_/4;     split16<<<(n4+255)/256, 256>>>(Wq, Wqh, Wql, n4); }
    { int n4 = P_*DH_/4;     split16<<<(n4+255)/256, 256>>>(Wk, Wkh, Wkl, n4); }
    { int n4 = B_*L_*DH_/4;  split16<<<(n4+255)/256, 256>>>(H,  Hh,  Hl,  n4); }
    zero_f32<<<(B_*T_+255)/256, 256>>>(sump, B_*T_);

    // 2) Q = Gh * (Wqh+Wql)^T -> Qh single fp16 [8192,256]
    gemm_2t<0><<<dim3(P_/128, (B_*T_)/128, 1), 256, T2_SMEM>>>(
        Gh, Wqh, Wql, Qh, nullptr, nullptr,
        B_*T_, P_, DG_, 0, 0, 0, 0, 1.f);

    // 3) K = Hh * (Wkh+Wkl)^T -> K hi/lo fp16 [32768,256]
    gemm_2t<1><<<dim3(P_/128, (B_*L_)/128, 1), 256, T2_SMEM>>>(
        Hh, Wkh, Wkl, Kh, Kl, nullptr,
        B_*L_, P_, DH_, 0, 0, 0, 0, 1.f);

    // 4) Ph = half(exp((Qh*(Kh+Kl)^T)/16)) + row sums over the rounded weights
    gemm_2t<3><<<dim3(L_/128, T_/128, B_), 256, T2_SMEM>>>(
        Qh, Kh, Kl, Ph, nullptr, sump,
        T_, L_, P_, (long)T_*P_, (long)L_*P_, (long)T_*L_, T_, 0.0625f);

    // 5) Z = (Ph * (Hh+Hl)) / (s+eps)   (NN, trans-B reads H directly)
    gemm_pv_nn<<<dim3(DH_/128, T_/128, B_), 256, PV_SMEM>>>(
        Ph, Hh, Hl, Z, sump,
        DH_, L_, (long)T_*L_, (long)L_*DH_, (long)T_*DH_, T_);
}

// round 14
// speedup vs baseline: 6.0009x; 1.4981x over previous
#include <cuda_runtime.h>
#include <cuda_fp16.h>
#include <cstdint>

// Problem: H[8,4096,1024] G[8,1024,768] Wq[256,768] Wk[256,1024] -> Z[8,1024,1024]
#define B_  8
#define L_  4096
#define DH_ 1024
#define T_  1024
#define DG_ 768
#define P_  256

// ---------------------------------------------------------------------------
// PTX helpers — base-target (sm_80+): mma.sync, ldmatrix, cp.async
// ---------------------------------------------------------------------------
__device__ __forceinline__ uint32_t smem_to_u32(const void* p) {
    uint32_t a;
    asm("{ .reg .u64 t; cvta.to.shared.u64 t, %1; cvt.u32.u64 %0, t; }" : "=r"(a) : "l"(p));
    return a;
}
#define CP_ASYNC16(sa, g) \
    asm volatile("cp.async.cg.shared.global [%0], [%1], 16;" :: "r"(sa), "l"(g))
#define CP_COMMIT() asm volatile("cp.async.commit_group;")
#define CP_WAIT1()  asm volatile("cp.async.wait_group 1;")

#define LDSM_X4(r0, r1, r2, r3, addr) \
    asm volatile("ldmatrix.sync.aligned.m8n8.x4.shared.b16 {%0,%1,%2,%3}, [%4];" \
                 : "=r"(r0), "=r"(r1), "=r"(r2), "=r"(r3) : "r"(addr))
#define LDSM_X4_T(r0, r1, r2, r3, addr) \
    asm volatile("ldmatrix.sync.aligned.m8n8.x4.trans.shared.b16 {%0,%1,%2,%3}, [%4];" \
                 : "=r"(r0), "=r"(r1), "=r"(r2), "=r"(r3) : "r"(addr))

// fp16 HMMA, fp32 accumulate
__device__ __forceinline__ void mma16816h(float* d, const uint32_t* a, const uint32_t* b) {
    asm volatile(
        "mma.sync.aligned.m16n8k16.row.col.f32.f16.f16.f32 "
        "{%0,%1,%2,%3}, {%4,%5,%6,%7}, {%8,%9}, {%0,%1,%2,%3};"
        : "+f"(d[0]), "+f"(d[1]), "+f"(d[2]), "+f"(d[3])
        : "r"(a[0]), "r"(a[1]), "r"(a[2]), "r"(a[3]), "r"(b[0]), "r"(b[1]));
}

__device__ __forceinline__ void splith(float f, __half& h, __half& l) {
    h = __float2half_rn(f);
    l = __float2half_rn(f - __half2float(h));
}
__device__ __forceinline__ uint32_t pack2h(__half a, __half b) {
    return ((uint32_t)*(uint16_t*)&b << 16) | *(uint16_t*)&a;
}

// ---------------------------------------------------------------------------
// Scratch (device globals; allocation-free)
// ---------------------------------------------------------------------------
__device__ __align__(16) __half g_Gh[(size_t)B_*T_*DG_];
__device__ __align__(16) __half g_Wqh[(size_t)P_*DG_],  g_Wql[(size_t)P_*DG_];
__device__ __align__(16) __half g_Wkh[(size_t)P_*DH_],  g_Wkl[(size_t)P_*DH_];
__device__ __align__(16) __half g_Hh[(size_t)B_*L_*DH_];
__device__ __align__(16) __half g_Qh[(size_t)B_*T_*P_];
__device__ __align__(16) __half g_Kh[(size_t)B_*L_*P_];
__device__ __align__(16) __half g_Ph[(size_t)B_*T_*L_];
__device__ float g_sum[(size_t)B_*T_];

// ---------------------------------------------------------------------------
// fp32 -> fp16 single
// ---------------------------------------------------------------------------
__global__ __launch_bounds__(256) void cvt16(
    const float* __restrict__ x, __half* __restrict__ hi, int n4)
{
    int i = blockIdx.x * 256 + threadIdx.x;
    if (i >= n4) return;
    float4 v = ((const float4*)x)[i];
    ((uint2*)hi)[i] = make_uint2(
        pack2h(__float2half_rn(v.x), __float2half_rn(v.y)),
        pack2h(__float2half_rn(v.z), __float2half_rn(v.w)));
}

// fp32 -> fp16 hi/lo split (weights only)
__global__ __launch_bounds__(256) void split16(
    const float* __restrict__ x, __half* __restrict__ hi,
    __half* __restrict__ lo, int n4)
{
    int i = blockIdx.x * 256 + threadIdx.x;
    if (i >= n4) return;
    float4 v = ((const float4*)x)[i];
    __half h0,h1,h2,h3,l0,l1,l2,l3;
    splith(v.x,h0,l0); splith(v.y,h1,l1); splith(v.z,h2,l2); splith(v.w,h3,l3);
    ((uint2*)hi)[i] = make_uint2(pack2h(h0,h1), pack2h(h2,h3));
    ((uint2*)lo)[i] = make_uint2(pack2h(l0,l1), pack2h(l2,l3));
}

__global__ __launch_bounds__(256) void zero_f32(float* __restrict__ p, int n) {
    int i = blockIdx.x * 256 + threadIdx.x;
    if (i < n) p[i] = 0.f;
}

// ---------------------------------------------------------------------------
// fp16 2-term NT GEMM (projections):  C[M,N] = half(A[M,K] * (Bhi+Blo)[N,K]^T)
// BM=BN=128, BK=32, 8 warps (2M x 4N), 2-stage cp.async, 2 CTAs/SM.
// ---------------------------------------------------------------------------
#define AROWB  80
#define TILEB  (128 * AROWB)        // 10240 B per operand tile
#define T2_STAGE (3 * TILEB)        // A, Bh, Bl = 30720
#define T2_SMEM  (2 * T2_STAGE)     // 61440

__global__ __launch_bounds__(256, 2) void gemm_2t(
    const __half* __restrict__ A,
    const __half* __restrict__ Bhi, const __half* __restrict__ Blo,
    __half* __restrict__ Ch,
    int M, int N, int K)
{
    extern __shared__ char smem[];
    const uint32_t sb = smem_to_u32(smem);
    const int tid  = threadIdx.x, wid = tid >> 5, lane = tid & 31;
    const int row0 = blockIdx.y * 128;
    const int col0 = blockIdx.x * 128;
    const int wm = (wid >> 2) * 64;
    const int wn = (wid & 3) * 32;

    const char* gT[3] = {
        (const char*)(A   + (long)row0 * K),
        (const char*)(Bhi + (long)col0 * K),
        (const char*)(Blo + (long)col0 * K) };
    const long ld = (long)K * 2;

    const int r_  = tid >> 2;
    const int cb_ = (tid & 3) * 16;
    const int NC  = K >> 5;

    auto load_stage = [&](int c) {
        const uint32_t s0 = sb + (uint32_t)((c & 1) * T2_STAGE);
        const long kb = (long)c * 64;
#pragma unroll
        for (int t = 0; t < 3; t++) {
            const char* g = gT[t] + kb;
#pragma unroll
            for (int i = 0; i < 2; i++) {
                const int row = r_ + i * 64;
                CP_ASYNC16(s0 + (uint32_t)(t * TILEB + row * AROWB + cb_),
                           g + (long)row * ld + cb_);
            }
        }
    };

    float acc[4][4][4];
#pragma unroll
    for (int a = 0; a < 4; a++)
#pragma unroll
        for (int b = 0; b < 4; b++)
#pragma unroll
            for (int q = 0; q < 4; q++) acc[a][b][q] = 0.f;

    load_stage(0); CP_COMMIT();
    load_stage(1); CP_COMMIT();

    const int aro = (wm + ((lane >> 3) & 1) * 8 + (lane & 7)) * AROWB + (lane >> 4) * 16;
    const int bro = (wn + (lane >> 4) * 8 + (lane & 7)) * AROWB + ((lane >> 3) & 1) * 16;

    for (int c = 0; c < NC; c++) {
        CP_WAIT1();
        __syncthreads();
        const uint32_t s0 = sb + (uint32_t)((c & 1) * T2_STAGE);

#pragma unroll
        for (int k16 = 0; k16 < 2; k16++) {
            const int kb = k16 * 32;
            uint32_t a_[4][4], bh[4][2], bl[4][2];
#pragma unroll
            for (int mt = 0; mt < 4; mt++)
                LDSM_X4(a_[mt][0], a_[mt][1], a_[mt][2], a_[mt][3],
                        s0 + (uint32_t)(aro + mt * (16 * AROWB) + kb));
#pragma unroll
            for (int p = 0; p < 2; p++) {
                LDSM_X4(bh[2*p][0], bh[2*p][1], bh[2*p+1][0], bh[2*p+1][1],
                        s0 + (uint32_t)(TILEB + bro + p * (16 * AROWB) + kb));
                LDSM_X4(bl[2*p][0], bl[2*p][1], bl[2*p+1][0], bl[2*p+1][1],
                        s0 + (uint32_t)(2 * TILEB + bro + p * (16 * AROWB) + kb));
            }
#pragma unroll
            for (int mt = 0; mt < 4; mt++)
#pragma unroll
                for (int nt = 0; nt < 4; nt++)
                    mma16816h(acc[mt][nt], a_[mt], bh[nt]);
#pragma unroll
            for (int mt = 0; mt < 4; mt++)
#pragma unroll
                for (int nt = 0; nt < 4; nt++)
                    mma16816h(acc[mt][nt], a_[mt], bl[nt]);
        }
        __syncthreads();
        if (c + 2 < NC) load_stage(c + 2);
        CP_COMMIT();
    }

    // ---- epilogue: single fp16 ----
#pragma unroll
    for (int mt = 0; mt < 4; mt++) {
        const int rg0 = row0 + wm + mt * 16 + (lane >> 2);
#pragma unroll
        for (int nt = 0; nt < 4; nt++) {
            const int cg = col0 + wn + nt * 8 + (lane & 3) * 2;
            const float* d = acc[mt][nt];
            const long o0 = (long)rg0 * N + cg;
            const long o1 = o0 + 8L * N;
            *(uint32_t*)(Ch + o0) = pack2h(__float2half_rn(d[0]), __float2half_rn(d[1]));
            *(uint32_t*)(Ch + o1) = pack2h(__float2half_rn(d[2]), __float2half_rn(d[3]));
        }
    }
}

// ---------------------------------------------------------------------------
// fp16 1-term NT GEMM (S):  ph = half(exp((Qh Kh^T) * scale)); row sums over
// the ROUNDED ph (PV normalizer exactly consistent).
// BM=BN=128, BK=32, 8 warps, 2-stage, 2 CTAs/SM.
// ---------------------------------------------------------------------------
#define T1_STAGE (2 * TILEB)        // A, B = 20480
#define T1_SMEM  (2 * T1_STAGE)     // 40960

__global__ __launch_bounds__(256, 2) void gemm_s_exp(
    const __half* __restrict__ A, const __half* __restrict__ Bq,
    __half* __restrict__ Ch, float* __restrict__ rowsums,
    int N, int K, long sA, long sB, long sC, long sRS, float scale)
{
    extern __shared__ char smem[];
    const uint32_t sb = smem_to_u32(smem);
    const int tid  = threadIdx.x, wid = tid >> 5, lane = tid & 31;
    const int row0 = blockIdx.y * 128;
    const int col0 = blockIdx.x * 128;
    const long zb  = blockIdx.z;
    const int wm = (wid >> 2) * 64;
    const int wn = (wid & 3) * 32;

    const char* gA = (const char*)(A  + zb * sA + (long)row0 * K);
    const char* gB = (const char*)(Bq + zb * sB + (long)col0 * K);
    const long ld = (long)K * 2;

    const int r_  = tid >> 2;
    const int cb_ = (tid & 3) * 16;
    const int NC  = K >> 5;

    auto load_stage = [&](int c) {
        const uint32_t s0 = sb + (uint32_t)((c & 1) * T1_STAGE);
        const long kb = (long)c * 64;
#pragma unroll
        for (int i = 0; i < 2; i++) {
            const int row = r_ + i * 64;
            CP_ASYNC16(s0 + (uint32_t)(row * AROWB + cb_), gA + kb + (long)row * ld + cb_);
            CP_ASYNC16(s0 + (uint32_t)(TILEB + row * AROWB + cb_),
                       gB + kb + (long)row * ld + cb_);
        }
    };

    float acc[4][4][4];
#pragma unroll
    for (int a = 0; a < 4; a++)
#pragma unroll
        for (int b = 0; b < 4; b++)
#pragma unroll
            for (int q = 0; q < 4; q++) acc[a][b][q] = 0.f;

    load_stage(0); CP_COMMIT();
    load_stage(1); CP_COMMIT();

    const int aro = (wm + ((lane >> 3) & 1) * 8 + (lane & 7)) * AROWB + (lane >> 4) * 16;
    const int bro = (wn + (lane >> 4) * 8 + (lane & 7)) * AROWB + ((lane >> 3) & 1) * 16;

    for (int c = 0; c < NC; c++) {
        CP_WAIT1();
        __syncthreads();
        const uint32_t s0 = sb + (uint32_t)((c & 1) * T1_STAGE);

#pragma unroll
        for (int k16 = 0; k16 < 2; k16++) {
            const int kb = k16 * 32;
            uint32_t a_[4][4], bh[4][2];
#pragma unroll
            for (int mt = 0; mt < 4; mt++)
                LDSM_X4(a_[mt][0], a_[mt][1], a_[mt][2], a_[mt][3],
                        s0 + (uint32_t)(aro + mt * (16 * AROWB) + kb));
#pragma unroll
            for (int p = 0; p < 2; p++)
                LDSM_X4(bh[2*p][0], bh[2*p][1], bh[2*p+1][0], bh[2*p+1][1],
                        s0 + (uint32_t)(TILEB + bro + p * (16 * AROWB) + kb));
#pragma unroll
            for (int mt = 0; mt < 4; mt++)
#pragma unroll
                for (int nt = 0; nt < 4; nt++)
                    mma16816h(acc[mt][nt], a_[mt], bh[nt]);
        }
        __syncthreads();
        if (c + 2 < NC) load_stage(c + 2);
        CP_COMMIT();
    }

    // ---- epilogue: exp + fp16 round + consistent row sums ----
    float* rowsum = (float*)smem;
    __syncthreads();
    if (tid < 128) rowsum[tid] = 0.f;
    __syncthreads();

#pragma unroll
    for (int mt = 0; mt < 4; mt++) {
        const int rl0 = wm + mt * 16 + (lane >> 2);
        const int rg0 = row0 + rl0;
        float s0a = 0.f, s1a = 0.f;
#pragma unroll
        for (int nt = 0; nt < 4; nt++) {
            const int cg = col0 + wn + nt * 8 + (lane & 3) * 2;
            const float* d = acc[mt][nt];
            __half p0 = __float2half_rn(__expf(d[0] * scale));
            __half p1 = __float2half_rn(__expf(d[1] * scale));
            __half p2 = __float2half_rn(__expf(d[2] * scale));
            __half p3 = __float2half_rn(__expf(d[3] * scale));
            s0a += __half2float(p0) + __half2float(p1);
            s1a += __half2float(p2) + __half2float(p3);
            const long o0 = zb * sC + (long)rg0 * N + cg;
            const long o1 = o0 + 8L * N;
            *(uint32_t*)(Ch + o0) = pack2h(p0, p1);
            *(uint32_t*)(Ch + o1) = pack2h(p2, p3);
        }
        s0a += __shfl_xor_sync(0xffffffffu, s0a, 1);
        s0a += __shfl_xor_sync(0xffffffffu, s0a, 2);
        s1a += __shfl_xor_sync(0xffffffffu, s1a, 1);
        s1a += __shfl_xor_sync(0xffffffffu, s1a, 2);
        if ((lane & 3) == 0) {
            atomicAdd(&rowsum[rl0],     s0a);
            atomicAdd(&rowsum[rl0 + 8], s1a);
        }
    }
    __syncthreads();
    if (tid < 128)
        atomicAdd(&rowsums[zb * sRS + row0 + tid], rowsum[tid]);
}

// ---------------------------------------------------------------------------
// PV GEMM (fp16 1-term, NN trans-B):
// Z[t,d] = (Σ_l Ph[t,l] * Hh[l,d]) / (s[t]+eps),  s = Σ_l Ph[t,l]
// BM=BN=128, BK=32, 8 warps, 2-stage cp.async, 2 CTAs/SM.
// ---------------------------------------------------------------------------
#define BROWB   272
#define BTILEB  (32 * BROWB)                 // 8704 B
#define PV_STAGE (TILEB + BTILEB)            // 18944
#define PV_SMEM  (2 * PV_STAGE)              // 37888

__global__ __launch_bounds__(256, 2) void gemm_pv1(
    const __half* __restrict__ Ah, const __half* __restrict__ Bq,
    float* __restrict__ C, const float* __restrict__ rowdiv,
    int N, int K, long sA, long sB, long sC, long sDiv)
{
    extern __shared__ char smem[];
    const uint32_t sb = smem_to_u32(smem);
    const int tid  = threadIdx.x, wid = tid >> 5, lane = tid & 31;
    const int row0 = blockIdx.y * 128;
    const int col0 = blockIdx.x * 128;
    const long zb  = blockIdx.z;
    const int wm = (wid >> 2) * 64;
    const int wn = (wid & 3) * 32;

    const char* gAh = (const char*)(Ah + zb * sA + (long)row0 * K);
    const char* gB  = (const char*)(Bq + zb * sB + col0);
    const long ldA = (long)K * 2;
    const long ldB = (long)DH_ * 2;

    const int NC = K >> 5;

    const int ar_  = tid >> 2;
    const int acb_ = (tid & 3) * 16;
    const int br_  = tid >> 4;         // 0..15
    const int bcb_ = (tid & 15) * 16;  // 0..240

    auto load_stage = [&](int c) {
        const uint32_t s0 = sb + (uint32_t)((c & 1) * PV_STAGE);
        const long kbA = (long)c * 64;
        const long krB = (long)c * 32;
#pragma unroll
        for (int i = 0; i < 2; i++) {
            const int row = ar_ + i * 64;
            CP_ASYNC16(s0 + (uint32_t)(row * AROWB + acb_),
                       gAh + kbA + (long)row * ldA + acb_);
        }
#pragma unroll
        for (int i = 0; i < 2; i++) {
            const int krow = br_ + i * 16;
            CP_ASYNC16(s0 + (uint32_t)(TILEB + krow * BROWB + bcb_),
                       gB + (krB + krow) * ldB + bcb_);
        }
    };

    float acc[4][4][4];
#pragma unroll
    for (int a = 0; a < 4; a++)
#pragma unroll
        for (int b = 0; b < 4; b++)
#pragma unroll
            for (int q = 0; q < 4; q++) acc[a][b][q] = 0.f;

    load_stage(0); CP_COMMIT();
    load_stage(1); CP_COMMIT();

    const int aro = (wm + ((lane >> 3) & 1) * 8 + (lane & 7)) * AROWB + (lane >> 4) * 16;
    const int btm = lane >> 3;
    const int bkr = (lane & 7) + (btm & 1) * 8;
    const int bco = (wn + (btm >> 1) * 8) * 2;

    for (int c = 0; c < NC; c++) {
        CP_WAIT1();
        __syncthreads();
        const uint32_t s0 = sb + (uint32_t)((c & 1) * PV_STAGE);

#pragma unroll
        for (int k16 = 0; k16 < 2; k16++) {
            const int kbA = k16 * 32;
            uint32_t a_[4][4], bh[4][2];
#pragma unroll
            for (int mt = 0; mt < 4; mt++)
                LDSM_X4(a_[mt][0], a_[mt][1], a_[mt][2], a_[mt][3],
                        s0 + (uint32_t)(aro + mt * (16 * AROWB) + kbA));
            const uint32_t bbase = s0 + (uint32_t)(TILEB + (k16 * 16 + bkr) * BROWB + bco);
#pragma unroll
            for (int p = 0; p < 2; p++)
                LDSM_X4_T(bh[2*p][0], bh[2*p][1], bh[2*p+1][0], bh[2*p+1][1],
                          bbase + (uint32_t)(p * 32));
#pragma unroll
            for (int mt = 0; mt < 4; mt++)
#pragma unroll
                for (int nt = 0; nt < 4; nt++)
                    mma16816h(acc[mt][nt], a_[mt], bh[nt]);
        }
        __syncthreads();
        if (c + 2 < NC) load_stage(c + 2);
        CP_COMMIT();
    }

    // ---- epilogue: divide by row sum ----
#pragma unroll
    for (int mt = 0; mt < 4; mt++) {
        const int rg0 = row0 + wm + mt * 16 + (lane >> 2);
        const int rg1 = rg0 + 8;
        const float m0 = 1.f / (rowdiv[zb * sDiv + rg0] + 1e-8f);
        const float m1 = 1.f / (rowdiv[zb * sDiv + rg1] + 1e-8f);
#pragma unroll
        for (int nt = 0; nt < 4; nt++) {
            const int cg = col0 + wn + nt * 8 + (lane & 3) * 2;
            const float* d = acc[mt][nt];
            *(float2*)(C + zb * sC + (long)rg0 * N + cg) = make_float2(d[0]*m0, d[1]*m0);
            *(float2*)(C + zb * sC + (long)rg1 * N + cg) = make_float2(d[2]*m1, d[3]*m1);
        }
    }
}

// ---------------------------------------------------------------------------
extern "C" void kernel_launch(void* const* d_in, const int* in_sizes, int n_in,
                              void* d_out, int out_size)
{
    const float* H  = (const float*)d_in[0];
    const float* G  = (const float*)d_in[1];
    const float* Wq = (const float*)d_in[2];
    const float* Wk = (const float*)d_in[3];
    float* Z = (float*)d_out;

    __half *Gh,*Wqh,*Wql,*Wkh,*Wkl,*Hh,*Qh,*Kh,*Ph;
    float *sump;
    cudaGetSymbolAddress((void**)&Gh,  g_Gh);
    cudaGetSymbolAddress((void**)&Wqh, g_Wqh);  cudaGetSymbolAddress((void**)&Wql, g_Wql);
    cudaGetSymbolAddress((void**)&Wkh, g_Wkh);  cudaGetSymbolAddress((void**)&Wkl, g_Wkl);
    cudaGetSymbolAddress((void**)&Hh,  g_Hh);
    cudaGetSymbolAddress((void**)&Qh,  g_Qh);
    cudaGetSymbolAddress((void**)&Kh,  g_Kh);
    cudaGetSymbolAddress((void**)&Ph,  g_Ph);
    cudaGetSymbolAddress((void**)&sump,g_sum);

    cudaFuncSetAttribute(gemm_2t,    cudaFuncAttributeMaxDynamicSharedMemorySize, T2_SMEM);
    cudaFuncSetAttribute(gemm_s_exp, cudaFuncAttributeMaxDynamicSharedMemorySize, T1_SMEM);
    cudaFuncSetAttribute(gemm_pv1,   cudaFuncAttributeMaxDynamicSharedMemorySize, PV_SMEM);

    // 1) fp16 conversions + zero row sums
    { int n4 = B_*T_*DG_/4;  cvt16  <<<(n4+255)/256, 256>>>(G,  Gh,  n4); }
    { int n4 = B_*L_*DH_/4;  cvt16  <<<(n4+255)/256, 256>>>(H,  Hh,  n4); }
    { int n4 = P_*DG_/4;     split16<<<(n4+255)/256, 256>>>(Wq, Wqh, Wql, n4); }
    { int n4 = P_*DH_/4;     split16<<<(n4+255)/256, 256>>>(Wk, Wkh, Wkl, n4); }
    zero_f32<<<(B_*T_+255)/256, 256>>>(sump, B_*T_);

    // 2) Q = Gh * (Wqh+Wql)^T -> Qh fp16 [8192,256]
    gemm_2t<<<dim3(P_/128, (B_*T_)/128, 1), 256, T2_SMEM>>>(
        Gh, Wqh, Wql, Qh, B_*T_, P_, DG_);

    // 3) K = Hh * (Wkh+Wkl)^T -> Kh fp16 [32768,256]
    gemm_2t<<<dim3(P_/128, (B_*L_)/128, 1), 256, T2_SMEM>>>(
        Hh, Wkh, Wkl, Kh, B_*L_, P_, DH_);

    // 4) Ph = half(exp((Qh Kh^T)/16)) + consistent row sums
    gemm_s_exp<<<dim3(L_/128, T_/128, B_), 256, T1_SMEM>>>(
        Qh, Kh, Ph, sump,
        L_, P_, (long)T_*P_, (long)L_*P_, (long)T_*L_, T_, 0.0625f);

    // 5) Z = (Ph * Hh) / (s+eps)   (NN, trans-B reads Hh directly)
    gemm_pv1<<<dim3(DH_/128, T_/128, B_), 256, PV_SMEM>>>(
        Ph, Hh, Z, sump,
        DH_, L_, (long)T_*L_, (long)L_*DH_, (long)T_*DH_, T_);
}

// round 15
// speedup vs baseline: 6.6083x; 1.1012x over previous
#include <cuda_runtime.h>
#include <cuda_fp16.h>
#include <cstdint>

// Problem: H[8,4096,1024] G[8,1024,768] Wq[256,768] Wk[256,1024] -> Z[8,1024,1024]
#define B_  8
#define L_  4096
#define DH_ 1024
#define T_  1024
#define DG_ 768
#define P_  256

// ---------------------------------------------------------------------------
// PTX helpers — base-target (sm_80+): mma.sync, ldmatrix, cp.async
// ---------------------------------------------------------------------------
__device__ __forceinline__ uint32_t smem_to_u32(const void* p) {
    uint32_t a;
    asm("{ .reg .u64 t; cvta.to.shared.u64 t, %1; cvt.u32.u64 %0, t; }" : "=r"(a) : "l"(p));
    return a;
}
#define CP_ASYNC16(sa, g) \
    asm volatile("cp.async.cg.shared.global [%0], [%1], 16;" :: "r"(sa), "l"(g))
#define CP_COMMIT() asm volatile("cp.async.commit_group;")
#define CP_WAIT1()  asm volatile("cp.async.wait_group 1;")

#define LDSM_X4(r0, r1, r2, r3, addr) \
    asm volatile("ldmatrix.sync.aligned.m8n8.x4.shared.b16 {%0,%1,%2,%3}, [%4];" \
                 : "=r"(r0), "=r"(r1), "=r"(r2), "=r"(r3) : "r"(addr))
#define LDSM_X4_T(r0, r1, r2, r3, addr) \
    asm volatile("ldmatrix.sync.aligned.m8n8.x4.trans.shared.b16 {%0,%1,%2,%3}, [%4];" \
                 : "=r"(r0), "=r"(r1), "=r"(r2), "=r"(r3) : "r"(addr))

// fp16 HMMA, fp32 accumulate
__device__ __forceinline__ void mma16816h(float* d, const uint32_t* a, const uint32_t* b) {
    asm volatile(
        "mma.sync.aligned.m16n8k16.row.col.f32.f16.f16.f32 "
        "{%0,%1,%2,%3}, {%4,%5,%6,%7}, {%8,%9}, {%0,%1,%2,%3};"
        : "+f"(d[0]), "+f"(d[1]), "+f"(d[2]), "+f"(d[3])
        : "r"(a[0]), "r"(a[1]), "r"(a[2]), "r"(a[3]), "r"(b[0]), "r"(b[1]));
}

__device__ __forceinline__ uint32_t pack2h(__half a, __half b) {
    return ((uint32_t)*(uint16_t*)&b << 16) | *(uint16_t*)&a;
}

// ---------------------------------------------------------------------------
// Scratch (device globals; allocation-free)
// ---------------------------------------------------------------------------
__device__ __align__(16) __half g_Gh[(size_t)B_*T_*DG_];
__device__ __align__(16) __half g_Wqh[(size_t)P_*DG_];
__device__ __align__(16) __half g_Wkh[(size_t)P_*DH_];
__device__ __align__(16) __half g_Hh[(size_t)B_*L_*DH_];
__device__ __align__(16) __half g_Qh[(size_t)B_*T_*P_];
__device__ __align__(16) __half g_Kh[(size_t)B_*L_*P_];
__device__ __align__(16) __half g_Ph[(size_t)B_*T_*L_];
__device__ float g_sum[(size_t)B_*T_];

// ---------------------------------------------------------------------------
// fp32 -> fp16
// ---------------------------------------------------------------------------
__global__ __launch_bounds__(256) void cvt16(
    const float* __restrict__ x, __half* __restrict__ hi, int n4)
{
    int i = blockIdx.x * 256 + threadIdx.x;
    if (i >= n4) return;
    float4 v = ((const float4*)x)[i];
    ((uint2*)hi)[i] = make_uint2(
        pack2h(__float2half_rn(v.x), __float2half_rn(v.y)),
        pack2h(__float2half_rn(v.z), __float2half_rn(v.w)));
}

__global__ __launch_bounds__(256) void zero_f32(float* __restrict__ p, int n) {
    int i = blockIdx.x * 256 + threadIdx.x;
    if (i < n) p[i] = 0.f;
}

// ---------------------------------------------------------------------------
// fp16 1-term NT GEMM:  C[M,N] = A[M,K] * B[N,K]^T
// BM=BN=128, BK=32, 8 warps (2M x 4N), 2-stage cp.async, 2 CTAs/SM.
// EPI 0: Ch = half(acc)                     (Q/K projections)
// EPI 1: ph = half(exp(acc*scale)); Ch = ph; row sums over ROUNDED ph  (S)
// ---------------------------------------------------------------------------
#define AROWB  80
#define TILEB  (128 * AROWB)        // 10240 B per operand tile
#define T1_STAGE (2 * TILEB)        // A, B = 20480
#define T1_SMEM  (2 * T1_STAGE)     // 40960

template<int EPI>
__global__ __launch_bounds__(256, 2) void gemm_1t(
    const __half* __restrict__ A, const __half* __restrict__ Bq,
    __half* __restrict__ Ch, float* __restrict__ rowsums,
    int N, int K, long sA, long sB, long sC, long sRS, float scale)
{
    extern __shared__ char smem[];
    const uint32_t sb = smem_to_u32(smem);
    const int tid  = threadIdx.x, wid = tid >> 5, lane = tid & 31;
    const int row0 = blockIdx.y * 128;
    const int col0 = blockIdx.x * 128;
    const long zb  = blockIdx.z;
    const int wm = (wid >> 2) * 64;
    const int wn = (wid & 3) * 32;

    const char* gA = (const char*)(A  + zb * sA + (long)row0 * K);
    const char* gB = (const char*)(Bq + zb * sB + (long)col0 * K);
    const long ld = (long)K * 2;

    const int r_  = tid >> 2;
    const int cb_ = (tid & 3) * 16;
    const int NC  = K >> 5;

    auto load_stage = [&](int c) {
        const uint32_t s0 = sb + (uint32_t)((c & 1) * T1_STAGE);
        const long kb = (long)c * 64;
#pragma unroll
        for (int i = 0; i < 2; i++) {
            const int row = r_ + i * 64;
            CP_ASYNC16(s0 + (uint32_t)(row * AROWB + cb_), gA + kb + (long)row * ld + cb_);
            CP_ASYNC16(s0 + (uint32_t)(TILEB + row * AROWB + cb_),
                       gB + kb + (long)row * ld + cb_);
        }
    };

    float acc[4][4][4];
#pragma unroll
    for (int a = 0; a < 4; a++)
#pragma unroll
        for (int b = 0; b < 4; b++)
#pragma unroll
            for (int q = 0; q < 4; q++) acc[a][b][q] = 0.f;

    load_stage(0); CP_COMMIT();
    load_stage(1); CP_COMMIT();

    const int aro = (wm + ((lane >> 3) & 1) * 8 + (lane & 7)) * AROWB + (lane >> 4) * 16;
    const int bro = (wn + (lane >> 4) * 8 + (lane & 7)) * AROWB + ((lane >> 3) & 1) * 16;

    for (int c = 0; c < NC; c++) {
        CP_WAIT1();
        __syncthreads();
        const uint32_t s0 = sb + (uint32_t)((c & 1) * T1_STAGE);

#pragma unroll
        for (int k16 = 0; k16 < 2; k16++) {
            const int kb = k16 * 32;
            uint32_t a_[4][4], bh[4][2];
#pragma unroll
            for (int mt = 0; mt < 4; mt++)
                LDSM_X4(a_[mt][0], a_[mt][1], a_[mt][2], a_[mt][3],
                        s0 + (uint32_t)(aro + mt * (16 * AROWB) + kb));
#pragma unroll
            for (int p = 0; p < 2; p++)
                LDSM_X4(bh[2*p][0], bh[2*p][1], bh[2*p+1][0], bh[2*p+1][1],
                        s0 + (uint32_t)(TILEB + bro + p * (16 * AROWB) + kb));
#pragma unroll
            for (int mt = 0; mt < 4; mt++)
#pragma unroll
                for (int nt = 0; nt < 4; nt++)
                    mma16816h(acc[mt][nt], a_[mt], bh[nt]);
        }
        __syncthreads();
        if (c + 2 < NC) load_stage(c + 2);
        CP_COMMIT();
    }

    // ---- epilogue ----
    float* rowsum = (float*)smem;
    if (EPI == 1) {
        __syncthreads();
        if (tid < 128) rowsum[tid] = 0.f;
        __syncthreads();
    }

#pragma unroll
    for (int mt = 0; mt < 4; mt++) {
        const int rl0 = wm + mt * 16 + (lane >> 2);
        const int rg0 = row0 + rl0;
        float s0a = 0.f, s1a = 0.f;
#pragma unroll
        for (int nt = 0; nt < 4; nt++) {
            const int cg = col0 + wn + nt * 8 + (lane & 3) * 2;
            const float* d = acc[mt][nt];
            const long o0 = zb * sC + (long)rg0 * N + cg;
            const long o1 = o0 + 8L * N;
            if (EPI == 1) {
                __half p0 = __float2half_rn(__expf(d[0] * scale));
                __half p1 = __float2half_rn(__expf(d[1] * scale));
                __half p2 = __float2half_rn(__expf(d[2] * scale));
                __half p3 = __float2half_rn(__expf(d[3] * scale));
                s0a += __half2float(p0) + __half2float(p1);
                s1a += __half2float(p2) + __half2float(p3);
                *(uint32_t*)(Ch + o0) = pack2h(p0, p1);
                *(uint32_t*)(Ch + o1) = pack2h(p2, p3);
            } else {
                *(uint32_t*)(Ch + o0) = pack2h(__float2half_rn(d[0]), __float2half_rn(d[1]));
                *(uint32_t*)(Ch + o1) = pack2h(__float2half_rn(d[2]), __float2half_rn(d[3]));
            }
        }
        if (EPI == 1) {
            s0a += __shfl_xor_sync(0xffffffffu, s0a, 1);
            s0a += __shfl_xor_sync(0xffffffffu, s0a, 2);
            s1a += __shfl_xor_sync(0xffffffffu, s1a, 1);
            s1a += __shfl_xor_sync(0xffffffffu, s1a, 2);
            if ((lane & 3) == 0) {
                atomicAdd(&rowsum[rl0],     s0a);
                atomicAdd(&rowsum[rl0 + 8], s1a);
            }
        }
    }
    if (EPI == 1) {
        __syncthreads();
        if (tid < 128)
            atomicAdd(&rowsums[zb * sRS + row0 + tid], rowsum[tid]);
    }
}

// ---------------------------------------------------------------------------
// PV GEMM (fp16 1-term, NN trans-B):
// Z[t,d] = (Σ_l Ph[t,l] * Hh[l,d]) / (s[t]+eps),  s = Σ_l Ph[t,l]
// BM=BN=128, BK=32, 8 warps, 2-stage cp.async, 2 CTAs/SM.
// ---------------------------------------------------------------------------
#define BROWB   272
#define BTILEB  (32 * BROWB)                 // 8704 B
#define PV_STAGE (TILEB + BTILEB)            // 18944
#define PV_SMEM  (2 * PV_STAGE)              // 37888

__global__ __launch_bounds__(256, 2) void gemm_pv1(
    const __half* __restrict__ Ah, const __half* __restrict__ Bq,
    float* __restrict__ C, const float* __restrict__ rowdiv,
    int N, int K, long sA, long sB, long sC, long sDiv)
{
    extern __shared__ char smem[];
    const uint32_t sb = smem_to_u32(smem);
    const int tid  = threadIdx.x, wid = tid >> 5, lane = tid & 31;
    const int row0 = blockIdx.y * 128;
    const int col0 = blockIdx.x * 128;
    const long zb  = blockIdx.z;
    const int wm = (wid >> 2) * 64;
    const int wn = (wid & 3) * 32;

    const char* gAh = (const char*)(Ah + zb * sA + (long)row0 * K);
    const char* gB  = (const char*)(Bq + zb * sB + col0);
    const long ldA = (long)K * 2;
    const long ldB = (long)DH_ * 2;

    const int NC = K >> 5;

    const int ar_  = tid >> 2;
    const int acb_ = (tid & 3) * 16;
    const int br_  = tid >> 4;         // 0..15
    const int bcb_ = (tid & 15) * 16;  // 0..240

    auto load_stage = [&](int c) {
        const uint32_t s0 = sb + (uint32_t)((c & 1) * PV_STAGE);
        const long kbA = (long)c * 64;
        const long krB = (long)c * 32;
#pragma unroll
        for (int i = 0; i < 2; i++) {
            const int row = ar_ + i * 64;
            CP_ASYNC16(s0 + (uint32_t)(row * AROWB + acb_),
                       gAh + kbA + (long)row * ldA + acb_);
        }
#pragma unroll
        for (int i = 0; i < 2; i++) {
            const int krow = br_ + i * 16;
            CP_ASYNC16(s0 + (uint32_t)(TILEB + krow * BROWB + bcb_),
                       gB + (krB + krow) * ldB + bcb_);
        }
    };

    float acc[4][4][4];
#pragma unroll
    for (int a = 0; a < 4; a++)
#pragma unroll
        for (int b = 0; b < 4; b++)
#pragma unroll
            for (int q = 0; q < 4; q++) acc[a][b][q] = 0.f;

    load_stage(0); CP_COMMIT();
    load_stage(1); CP_COMMIT();

    const int aro = (wm + ((lane >> 3) & 1) * 8 + (lane & 7)) * AROWB + (lane >> 4) * 16;
    const int btm = lane >> 3;
    const int bkr = (lane & 7) + (btm & 1) * 8;
    const int bco = (wn + (btm >> 1) * 8) * 2;

    for (int c = 0; c < NC; c++) {
        CP_WAIT1();
        __syncthreads();
        const uint32_t s0 = sb + (uint32_t)((c & 1) * PV_STAGE);

#pragma unroll
        for (int k16 = 0; k16 < 2; k16++) {
            const int kbA = k16 * 32;
            uint32_t a_[4][4], bh[4][2];
#pragma unroll
            for (int mt = 0; mt < 4; mt++)
                LDSM_X4(a_[mt][0], a_[mt][1], a_[mt][2], a_[mt][3],
                        s0 + (uint32_t)(aro + mt * (16 * AROWB) + kbA));
            const uint32_t bbase = s0 + (uint32_t)(TILEB + (k16 * 16 + bkr) * BROWB + bco);
#pragma unroll
            for (int p = 0; p < 2; p++)
                LDSM_X4_T(bh[2*p][0], bh[2*p][1], bh[2*p+1][0], bh[2*p+1][1],
                          bbase + (uint32_t)(p * 32));
#pragma unroll
            for (int mt = 0; mt < 4; mt++)
#pragma unroll
                for (int nt = 0; nt < 4; nt++)
                    mma16816h(acc[mt][nt], a_[mt], bh[nt]);
        }
        __syncthreads();
        if (c + 2 < NC) load_stage(c + 2);
        CP_COMMIT();
    }

    // ---- epilogue: divide by row sum ----
#pragma unroll
    for (int mt = 0; mt < 4; mt++) {
        const int rg0 = row0 + wm + mt * 16 + (lane >> 2);
        const int rg1 = rg0 + 8;
        const float m0 = 1.f / (rowdiv[zb * sDiv + rg0] + 1e-8f);
        const float m1 = 1.f / (rowdiv[zb * sDiv + rg1] + 1e-8f);
#pragma unroll
        for (int nt = 0; nt < 4; nt++) {
            const int cg = col0 + wn + nt * 8 + (lane & 3) * 2;
            const float* d = acc[mt][nt];
            *(float2*)(C + zb * sC + (long)rg0 * N + cg) = make_float2(d[0]*m0, d[1]*m0);
            *(float2*)(C + zb * sC + (long)rg1 * N + cg) = make_float2(d[2]*m1, d[3]*m1);
        }
    }
}

// ---------------------------------------------------------------------------
extern "C" void kernel_launch(void* const* d_in, const int* in_sizes, int n_in,
                              void* d_out, int out_size)
{
    const float* H  = (const float*)d_in[0];
    const float* G  = (const float*)d_in[1];
    const float* Wq = (const float*)d_in[2];
    const float* Wk = (const float*)d_in[3];
    float* Z = (float*)d_out;

    __half *Gh,*Wqh,*Wkh,*Hh,*Qh,*Kh,*Ph;
    float *sump;
    cudaGetSymbolAddress((void**)&Gh,  g_Gh);
    cudaGetSymbolAddress((void**)&Wqh, g_Wqh);
    cudaGetSymbolAddress((void**)&Wkh, g_Wkh);
    cudaGetSymbolAddress((void**)&Hh,  g_Hh);
    cudaGetSymbolAddress((void**)&Qh,  g_Qh);
    cudaGetSymbolAddress((void**)&Kh,  g_Kh);
    cudaGetSymbolAddress((void**)&Ph,  g_Ph);
    cudaGetSymbolAddress((void**)&sump,g_sum);

    cudaFuncSetAttribute(gemm_1t<0>, cudaFuncAttributeMaxDynamicSharedMemorySize, T1_SMEM);
    cudaFuncSetAttribute(gemm_1t<1>, cudaFuncAttributeMaxDynamicSharedMemorySize, T1_SMEM);
    cudaFuncSetAttribute(gemm_pv1,   cudaFuncAttributeMaxDynamicSharedMemorySize, PV_SMEM);

    // 1) fp16 conversions + zero row sums
    { int n4 = B_*T_*DG_/4;  cvt16<<<(n4+255)/256, 256>>>(G,  Gh,  n4); }
    { int n4 = B_*L_*DH_/4;  cvt16<<<(n4+255)/256, 256>>>(H,  Hh,  n4); }
    { int n4 = P_*DG_/4;     cvt16<<<(n4+255)/256, 256>>>(Wq, Wqh, n4); }
    { int n4 = P_*DH_/4;     cvt16<<<(n4+255)/256, 256>>>(Wk, Wkh, n4); }
    zero_f32<<<(B_*T_+255)/256, 256>>>(sump, B_*T_);

    // 2) Q = half(Gh Wqh^T)  [8192,256]
    gemm_1t<0><<<dim3(P_/128, (B_*T_)/128, 1), 256, T1_SMEM>>>(
        Gh, Wqh, Qh, nullptr, P_, DG_, 0, 0, 0, 0, 1.f);

    // 3) K = half(Hh Wkh^T)  [32768,256]
    gemm_1t<0><<<dim3(P_/128, (B_*L_)/128, 1), 256, T1_SMEM>>>(
        Hh, Wkh, Kh, nullptr, P_, DH_, 0, 0, 0, 0, 1.f);

    // 4) Ph = half(exp((Qh Kh^T)/16)) + consistent row sums
    gemm_1t<1><<<dim3(L_/128, T_/128, B_), 256, T1_SMEM>>>(
        Qh, Kh, Ph, sump,
        L_, P_, (long)T_*P_, (long)L_*P_, (long)T_*L_, T_, 0.0625f);

    // 5) Z = (Ph * Hh) / (s+eps)   (NN, trans-B reads Hh directly)
    gemm_pv1<<<dim3(DH_/128, T_/128, B_), 256, PV_SMEM>>>(
        Ph, Hh, Z, sump,
        DH_, L_, (long)T_*L_, (long)L_*DH_, (long)T_*DH_, T_);
}